// round 11
// baseline (speedup 1.0000x reference)
#include <cuda_runtime.h>
#include <cuda_bf16.h>
#include <stdint.h>
#include <math.h>

#define Bb   8
#define Nn   1024
#define INc  256
#define AXc  512
#define Dd   768
#define OUTc 256
#define ALPHA 0.2f
#define NEGV  -9.0e15f

typedef __nv_bfloat16 bf16;

// ---------------- scratch (static device globals; no allocation) ----------------
__device__ float g_M[OUTc * INc];
__device__ float g_v1[INc], g_v2[INc];
__device__ float g_zb[OUTc];
__device__ float g_c[2];
__device__ __align__(16) float g_f1[Bb * Nn];
__device__ __align__(16) float g_f2[Bb * Nn];

__device__ __align__(16) bf16 g_att_h[(size_t)Bb * Nn * Nn];
__device__ __align__(16) bf16 g_att_l[(size_t)Bb * Nn * Nn];
__device__ __align__(16) bf16 g_X_h[(size_t)Bb * Nn * Dd];
__device__ __align__(16) bf16 g_X_l[(size_t)Bb * Nn * Dd];
__device__ __align__(16) bf16 g_W_h[OUTc * Dd];
__device__ __align__(16) bf16 g_W_l[OUTc * Dd];
__device__ __align__(16) bf16 g_z_h[(size_t)Bb * OUTc * Nn];
__device__ __align__(16) bf16 g_z_l[(size_t)Bb * OUTc * Nn];

__device__ __forceinline__ void split_bf16(float v, bf16& h, bf16& l) {
    h = __float2bfloat16(v);
    l = __float2bfloat16(v - __bfloat162float(h));
}

__device__ __forceinline__ uint32_t pack2(bf16 a, bf16 b) {
    return (uint32_t)__bfloat16_as_ushort(a) | ((uint32_t)__bfloat16_as_ushort(b) << 16);
}

__device__ __forceinline__ void ldsm4(uint32_t& r0, uint32_t& r1, uint32_t& r2,
                                      uint32_t& r3, uint32_t addr) {
    asm volatile(
        "ldmatrix.sync.aligned.m8n8.x4.shared.b16 {%0,%1,%2,%3}, [%4];"
        : "=r"(r0), "=r"(r1), "=r"(r2), "=r"(r3) : "r"(addr));
}

__device__ __forceinline__ void mma16816(float& c0, float& c1, float& c2, float& c3,
                                         uint32_t a0, uint32_t a1, uint32_t a2, uint32_t a3,
                                         uint32_t b0, uint32_t b1) {
    asm volatile(
        "mma.sync.aligned.m16n8k16.row.col.f32.bf16.bf16.f32 "
        "{%0,%1,%2,%3},{%4,%5,%6,%7},{%8,%9},{%0,%1,%2,%3};"
        : "+f"(c0), "+f"(c1), "+f"(c2), "+f"(c3)
        : "r"(a0), "r"(a1), "r"(a2), "r"(a3), "r"(b0), "r"(b1));
}

// ---------------- prep ----------------
__global__ void prep_M(const float* __restrict__ fc_w, const float* __restrict__ WQ) {
    int o = blockIdx.x, k = threadIdx.x;
    const float* fr = fc_w + o * Dd;
    float s = 0.f;
    for (int t = 0; t < INc; ++t) s += fr[t] * WQ[t * INc + k];
    g_M[o * INc + k] = s;
}

__global__ void prep_small(const float* __restrict__ WQ, const float* __restrict__ WQb,
                           const float* __restrict__ a, const float* __restrict__ fc_w) {
    int t = threadIdx.x;
    float s1 = 0.f, s2 = 0.f;
    for (int r = 0; r < INc; ++r) {
        float w = WQ[r * INc + t];
        s1 += w * a[r];
        s2 += w * a[Dd + r];
    }
    g_v1[t] = s1; g_v2[t] = s2;
    const float* fr = fc_w + t * Dd;
    float z = 0.f;
    for (int r = 0; r < INc; ++r) z += WQb[r] * fr[r];
    g_zb[t] = z;
    __shared__ float r1[256], r2[256];
    r1[t] = WQb[t] * a[t];
    r2[t] = WQb[t] * a[Dd + t];
    __syncthreads();
    for (int st = 128; st > 0; st >>= 1) {
        if (t < st) { r1[t] += r1[t + st]; r2[t] += r2[t + st]; }
        __syncthreads();
    }
    if (t == 0) { g_c[0] = r1[0]; g_c[1] = r2[0]; }
}

__global__ void conv_w(const float* __restrict__ fc_w) {
    int idx = blockIdx.x * 256 + threadIdx.x;
    int o = idx / Dd, k = idx - o * Dd;
    float v = (k < INc) ? g_M[o * INc + k] : fc_w[o * Dd + k];
    bf16 h, l; split_bf16(v, h, l);
    g_W_h[idx] = h; g_W_l[idx] = l;
}

__global__ __launch_bounds__(256) void conv_x(const float* __restrict__ x,
                                              const float* __restrict__ ax) {
    __shared__ float tile[32][33];
    int b = blockIdx.z;
    int k0 = blockIdx.x * 32, n0 = blockIdx.y * 32;
    int t = threadIdx.x;
    int tn = t & 31, tk = t >> 5;
    #pragma unroll
    for (int u = 0; u < 4; ++u) {
        int kk = k0 + tk + 8 * u;
        float vv = (kk < INc) ? x[((size_t)b * INc + kk) * Nn + n0 + tn]
                              : ax[((size_t)b * AXc + (kk - INc)) * Nn + n0 + tn];
        tile[tk + 8 * u][tn] = vv;
    }
    __syncthreads();
    int wn = t >> 3, wk = (t & 7) * 4;
    bf16 h[4], l[4];
    #pragma unroll
    for (int u = 0; u < 4; ++u) split_bf16(tile[wk + u][wn], h[u], l[u]);
    size_t idx = ((size_t)b * Nn + n0 + wn) * Dd + k0 + wk;
    *(uint2*)(g_X_h + idx) = make_uint2(pack2(h[0], h[1]), pack2(h[2], h[3]));
    *(uint2*)(g_X_l + idx) = make_uint2(pack2(l[0], l[1]), pack2(l[2], l[3]));
}

// ---------------- f1/f2 ----------------
__global__ void f_kernel(const float* __restrict__ x, const float* __restrict__ ax,
                         const float* __restrict__ a) {
    int b  = blockIdx.y;
    int n  = blockIdx.x * 32 + threadIdx.x;
    int ty = threadIdx.y;
    const float* xb  = x  + (size_t)b * INc * Nn;
    const float* axb = ax + (size_t)b * AXc * Nn;
    float s1 = 0.f, s2 = 0.f;
    for (int k = ty; k < INc; k += 8) {
        float v = xb[k * Nn + n];
        s1 += v * g_v1[k];
        s2 += v * g_v2[k];
    }
    for (int c = ty; c < AXc; c += 8) {
        float v = axb[c * Nn + n];
        s1 += v * a[INc + c];
        s2 += v * a[Dd + INc + c];
    }
    __shared__ float r1[8][32], r2[8][32];
    r1[ty][threadIdx.x] = s1;
    r2[ty][threadIdx.x] = s2;
    __syncthreads();
    if (ty == 0) {
        float t1 = 0.f, t2 = 0.f;
        #pragma unroll
        for (int u = 0; u < 8; ++u) { t1 += r1[u][threadIdx.x]; t2 += r2[u][threadIdx.x]; }
        g_f1[b * Nn + n] = t1 + g_c[0];
        g_f2[b * Nn + n] = t2 + g_c[1];
    }
}

// ---------------- fused attz: blocks 0..127 = z GEMM tiles, 128.. = softmax rows ----------------
#define SROW 24
#define BUFB (128 * SROW * 2)
#define BUFU (128 * 3)

__global__ __launch_bounds__(256) void attz_mma(const int* __restrict__ adj) {
    __shared__ __align__(16) bf16 sAh[2 * 128 * SROW], sAl[2 * 128 * SROW];
    __shared__ __align__(16) bf16 sBh[2 * 128 * SROW], sBl[2 * 128 * SROW];
    int t = threadIdx.x;

    if (blockIdx.x < 128) {
        // ---------- z role: z^T[o][n] = Wcat @ Xcat^T, M=256, N=1024, K=768 ----------
        const int K = Dd;
        int zi = blockIdx.x;
        int b  = zi >> 4;
        int m0 = ((zi >> 3) & 1) * 128;
        int n0 = (zi & 7) * 128;
        const bf16* Ah = g_W_h;
        const bf16* Al = g_W_l;
        const bf16* Bh = g_X_h + (size_t)b * Nn * Dd;
        const bf16* Bl = g_X_l + (size_t)b * Nn * Dd;

        int lrow = t >> 1, lhalf = t & 1;
        const bf16* pAh = Ah + (size_t)(m0 + lrow) * K + lhalf * 8;
        const bf16* pAl = Al + (size_t)(m0 + lrow) * K + lhalf * 8;
        const bf16* pBh = Bh + (size_t)(n0 + lrow) * K + lhalf * 8;
        const bf16* pBl = Bl + (size_t)(n0 + lrow) * K + lhalf * 8;
        int sidx = lrow * 3 + lhalf;

        int wid = t >> 5, lane = t & 31;
        int wm0 = (wid >> 2) * 64;
        int wn0 = (wid & 3) * 32;
        int lr = lane & 15, lc = (lane >> 4) * 8;

        uint32_t saAh = (uint32_t)__cvta_generic_to_shared(sAh);
        uint32_t saAl = (uint32_t)__cvta_generic_to_shared(sAl);
        uint32_t saBh = (uint32_t)__cvta_generic_to_shared(sBh);
        uint32_t saBl = (uint32_t)__cvta_generic_to_shared(sBl);
        uint32_t aAddrH[4], aAddrL[4], bAddrH[2], bAddrL[2];
        #pragma unroll
        for (int mb = 0; mb < 4; ++mb) {
            uint32_t off = (uint32_t)((wm0 + mb * 16 + lr) * SROW + lc) * 2;
            aAddrH[mb] = saAh + off;
            aAddrL[mb] = saAl + off;
        }
        #pragma unroll
        for (int g = 0; g < 2; ++g) {
            uint32_t off = (uint32_t)((wn0 + g * 16 + lr) * SROW + lc) * 2;
            bAddrH[g] = saBh + off;
            bAddrL[g] = saBl + off;
        }

        float acc[4][4][4];
        #pragma unroll
        for (int i = 0; i < 4; ++i)
            #pragma unroll
            for (int j = 0; j < 4; ++j)
                #pragma unroll
                for (int q = 0; q < 4; ++q) acc[i][j][q] = 0.f;

        uint4 fa  = *(const uint4*)pAh;
        uint4 fb  = *(const uint4*)pAl;
        uint4 fc4 = *(const uint4*)pBh;
        uint4 fd  = *(const uint4*)pBl;
        ((uint4*)sAh)[sidx] = fa;
        ((uint4*)sAl)[sidx] = fb;
        ((uint4*)sBh)[sidx] = fc4;
        ((uint4*)sBl)[sidx] = fd;
        __syncthreads();

        uint32_t Afh[4][4], Afl[4][4], Bfh[2][4], Bfl[2][4];
        int cur = 0;

        for (int k0 = 0; k0 < K; k0 += 16) {
            bool has_next = (k0 + 16 < K);
            if (has_next) {
                fa  = *(const uint4*)(pAh + k0 + 16);
                fb  = *(const uint4*)(pAl + k0 + 16);
                fc4 = *(const uint4*)(pBh + k0 + 16);
                fd  = *(const uint4*)(pBl + k0 + 16);
            }
            uint32_t co = (uint32_t)cur * BUFB;
            #pragma unroll
            for (int mb = 0; mb < 4; ++mb) {
                ldsm4(Afh[mb][0], Afh[mb][1], Afh[mb][2], Afh[mb][3], aAddrH[mb] + co);
                ldsm4(Afl[mb][0], Afl[mb][1], Afl[mb][2], Afl[mb][3], aAddrL[mb] + co);
            }
            #pragma unroll
            for (int g = 0; g < 2; ++g) {
                ldsm4(Bfh[g][0], Bfh[g][1], Bfh[g][2], Bfh[g][3], bAddrH[g] + co);
                ldsm4(Bfl[g][0], Bfl[g][1], Bfl[g][2], Bfl[g][3], bAddrL[g] + co);
            }
            #pragma unroll
            for (int mb = 0; mb < 4; ++mb) {
                #pragma unroll
                for (int j = 0; j < 4; ++j) {
                    int g = j >> 1, p = j & 1;
                    float* C = acc[mb][j];
                    mma16816(C[0], C[1], C[2], C[3],
                             Afh[mb][0], Afh[mb][1], Afh[mb][2], Afh[mb][3],
                             Bfh[g][p], Bfh[g][p + 2]);
                    mma16816(C[0], C[1], C[2], C[3],
                             Afh[mb][0], Afh[mb][1], Afh[mb][2], Afh[mb][3],
                             Bfl[g][p], Bfl[g][p + 2]);
                    mma16816(C[0], C[1], C[2], C[3],
                             Afl[mb][0], Afl[mb][1], Afl[mb][2], Afl[mb][3],
                             Bfh[g][p], Bfh[g][p + 2]);
                }
            }
            if (has_next) {
                int nidx = (cur ^ 1) * BUFU + sidx;
                ((uint4*)sAh)[nidx] = fa;
                ((uint4*)sAl)[nidx] = fb;
                ((uint4*)sBh)[nidx] = fc4;
                ((uint4*)sBl)[nidx] = fd;
            }
            __syncthreads();
            cur ^= 1;
        }

        int r_lo = lane >> 2, c_off = (lane & 3) * 2;
        size_t base = (size_t)b * OUTc * Nn;
        #pragma unroll
        for (int mb = 0; mb < 4; ++mb) {
            #pragma unroll
            for (int j = 0; j < 4; ++j) {
                int row = m0 + wm0 + mb * 16 + r_lo;
                int col = n0 + wn0 + j * 8 + c_off;
                float* C = acc[mb][j];
                #pragma unroll
                for (int h = 0; h < 2; ++h) {
                    int rr = row + h * 8;
                    float bz = g_zb[rr];
                    float v0 = C[h * 2 + 0] + bz;
                    float v1 = C[h * 2 + 1] + bz;
                    bf16 h0, l0, h1, l1;
                    split_bf16(v0, h0, l0);
                    split_bf16(v1, h1, l1);
                    size_t idx = base + (size_t)rr * Nn + col;
                    *(uint32_t*)(g_z_h + idx) = pack2(h0, h1);
                    *(uint32_t*)(g_z_l + idx) = pack2(l0, l1);
                }
            }
        }
    } else {
        // ---------- att role: masked softmax row -> bf16 hi/lo ----------
        int bid = blockIdx.x - 128;
        int b = bid >> 10, i = bid & 1023;
        int lane = t & 31, warp = t >> 5;
        float* red = (float*)sAh;   // alias z smem: 16 floats used

        float f1v = g_f1[b * Nn + i];
        const int4*   arow = (const int4*)(adj + ((size_t)b * Nn + i) * Nn);
        const float4* f2r  = (const float4*)(g_f2 + b * Nn);
        float4 f2 = f2r[t];
        int4   ad = arow[t];
        float v[4];
        v[0] = f1v + f2.x; v[1] = f1v + f2.y; v[2] = f1v + f2.z; v[3] = f1v + f2.w;
        #pragma unroll
        for (int q = 0; q < 4; ++q) v[q] = v[q] > 0.f ? v[q] : ALPHA * v[q];
        v[0] = (ad.x > 0) ? v[0] : NEGV;
        v[1] = (ad.y > 0) ? v[1] : NEGV;
        v[2] = (ad.z > 0) ? v[2] : NEGV;
        v[3] = (ad.w > 0) ? v[3] : NEGV;

        float m = fmaxf(fmaxf(v[0], v[1]), fmaxf(v[2], v[3]));
        #pragma unroll
        for (int o = 16; o > 0; o >>= 1) m = fmaxf(m, __shfl_xor_sync(0xffffffffu, m, o));
        if (lane == 0) red[warp] = m;
        __syncthreads();
        m = red[0];
        #pragma unroll
        for (int u = 1; u < 8; ++u) m = fmaxf(m, red[u]);

        float p[4], s = 0.f;
        #pragma unroll
        for (int q = 0; q < 4; ++q) { p[q] = __expf(v[q] - m); s += p[q]; }
        #pragma unroll
        for (int o = 16; o > 0; o >>= 1) s += __shfl_xor_sync(0xffffffffu, s, o);
        if (lane == 0) red[8 + warp] = s;
        __syncthreads();
        s = red[8];
        #pragma unroll
        for (int u = 1; u < 8; ++u) s += red[8 + u];
        float inv = 1.f / s;

        bf16 h[4], l[4];
        #pragma unroll
        for (int q = 0; q < 4; ++q) split_bf16(p[q] * inv, h[q], l[q]);
        size_t base = ((size_t)b * Nn + i) * Nn + t * 4;
        *(uint2*)(g_att_h + base) = make_uint2(pack2(h[0], h[1]), pack2(h[2], h[3]));
        *(uint2*)(g_att_l + base) = make_uint2(pack2(l[0], l[1]), pack2(l[2], l[3]));
    }
}

// ---------------- out = elu(att @ z^T + fc_b) : M=1024, N=256, K=1024 ----------------
__global__ __launch_bounds__(256) void out_mma(const float* __restrict__ bias,
                                               float* __restrict__ outF) {
    const int K = Nn;
    int b  = blockIdx.z;
    int m0 = blockIdx.y * 128;
    int n0 = blockIdx.x * 128;
    const bf16* Ah = g_att_h + (size_t)b * Nn * Nn;
    const bf16* Al = g_att_l + (size_t)b * Nn * Nn;
    const bf16* Bh = g_z_h + (size_t)b * OUTc * Nn;
    const bf16* Bl = g_z_l + (size_t)b * OUTc * Nn;

    __shared__ __align__(16) bf16 sAh[2 * 128 * SROW], sAl[2 * 128 * SROW];
    __shared__ __align__(16) bf16 sBh[2 * 128 * SROW], sBl[2 * 128 * SROW];

    int t = threadIdx.x;
    int lrow = t >> 1, lhalf = t & 1;
    const bf16* pAh = Ah + (size_t)(m0 + lrow) * K + lhalf * 8;
    const bf16* pAl = Al + (size_t)(m0 + lrow) * K + lhalf * 8;
    const bf16* pBh = Bh + (size_t)(n0 + lrow) * K + lhalf * 8;
    const bf16* pBl = Bl + (size_t)(n0 + lrow) * K + lhalf * 8;
    int sidx = lrow * 3 + lhalf;

    int wid = t >> 5, lane = t & 31;
    int wm0 = (wid >> 2) * 64;
    int wn0 = (wid & 3) * 32;
    int lr = lane & 15, lc = (lane >> 4) * 8;

    uint32_t saAh = (uint32_t)__cvta_generic_to_shared(sAh);
    uint32_t saAl = (uint32_t)__cvta_generic_to_shared(sAl);
    uint32_t saBh = (uint32_t)__cvta_generic_to_shared(sBh);
    uint32_t saBl = (uint32_t)__cvta_generic_to_shared(sBl);
    uint32_t aAddrH[4], aAddrL[4], bAddrH[2], bAddrL[2];
    #pragma unroll
    for (int mb = 0; mb < 4; ++mb) {
        uint32_t off = (uint32_t)((wm0 + mb * 16 + lr) * SROW + lc) * 2;
        aAddrH[mb] = saAh + off;
        aAddrL[mb] = saAl + off;
    }
    #pragma unroll
    for (int g = 0; g < 2; ++g) {
        uint32_t off = (uint32_t)((wn0 + g * 16 + lr) * SROW + lc) * 2;
        bAddrH[g] = saBh + off;
        bAddrL[g] = saBl + off;
    }

    float acc[4][4][4];
    #pragma unroll
    for (int i = 0; i < 4; ++i)
        #pragma unroll
        for (int j = 0; j < 4; ++j)
            #pragma unroll
            for (int q = 0; q < 4; ++q) acc[i][j][q] = 0.f;

    uint4 fa  = *(const uint4*)pAh;
    uint4 fb  = *(const uint4*)pAl;
    uint4 fc4 = *(const uint4*)pBh;
    uint4 fd  = *(const uint4*)pBl;
    ((uint4*)sAh)[sidx] = fa;
    ((uint4*)sAl)[sidx] = fb;
    ((uint4*)sBh)[sidx] = fc4;
    ((uint4*)sBl)[sidx] = fd;
    __syncthreads();

    uint32_t Afh[4][4], Afl[4][4], Bfh[2][4], Bfl[2][4];
    int cur = 0;

    for (int k0 = 0; k0 < K; k0 += 16) {
        bool has_next = (k0 + 16 < K);
        if (has_next) {
            fa  = *(const uint4*)(pAh + k0 + 16);
            fb  = *(const uint4*)(pAl + k0 + 16);
            fc4 = *(const uint4*)(pBh + k0 + 16);
            fd  = *(const uint4*)(pBl + k0 + 16);
        }
        uint32_t co = (uint32_t)cur * BUFB;
        #pragma unroll
        for (int mb = 0; mb < 4; ++mb) {
            ldsm4(Afh[mb][0], Afh[mb][1], Afh[mb][2], Afh[mb][3], aAddrH[mb] + co);
            ldsm4(Afl[mb][0], Afl[mb][1], Afl[mb][2], Afl[mb][3], aAddrL[mb] + co);
        }
        #pragma unroll
        for (int g = 0; g < 2; ++g) {
            ldsm4(Bfh[g][0], Bfh[g][1], Bfh[g][2], Bfh[g][3], bAddrH[g] + co);
            ldsm4(Bfl[g][0], Bfl[g][1], Bfl[g][2], Bfl[g][3], bAddrL[g] + co);
        }
        #pragma unroll
        for (int mb = 0; mb < 4; ++mb) {
            #pragma unroll
            for (int j = 0; j < 4; ++j) {
                int g = j >> 1, p = j & 1;
                float* C = acc[mb][j];
                mma16816(C[0], C[1], C[2], C[3],
                         Afh[mb][0], Afh[mb][1], Afh[mb][2], Afh[mb][3],
                         Bfh[g][p], Bfh[g][p + 2]);
                mma16816(C[0], C[1], C[2], C[3],
                         Afh[mb][0], Afh[mb][1], Afh[mb][2], Afh[mb][3],
                         Bfl[g][p], Bfl[g][p + 2]);
                mma16816(C[0], C[1], C[2], C[3],
                         Afl[mb][0], Afl[mb][1], Afl[mb][2], Afl[mb][3],
                         Bfh[g][p], Bfh[g][p + 2]);
            }
        }
        if (has_next) {
            int nidx = (cur ^ 1) * BUFU + sidx;
            ((uint4*)sAh)[nidx] = fa;
            ((uint4*)sAl)[nidx] = fb;
            ((uint4*)sBh)[nidx] = fc4;
            ((uint4*)sBl)[nidx] = fd;
        }
        __syncthreads();
        cur ^= 1;
    }

    int r_lo = lane >> 2, c_off = (lane & 3) * 2;
    size_t base = (size_t)b * Nn * OUTc;
    #pragma unroll
    for (int mb = 0; mb < 4; ++mb) {
        #pragma unroll
        for (int j = 0; j < 4; ++j) {
            int row = m0 + wm0 + mb * 16 + r_lo;
            int col = n0 + wn0 + j * 8 + c_off;
            float* C = acc[mb][j];
            #pragma unroll
            for (int h = 0; h < 2; ++h) {
                int rr = row + h * 8;
                float v0 = C[h * 2 + 0] + bias[col + 0];
                float v1 = C[h * 2 + 1] + bias[col + 1];
                v0 = v0 > 0.f ? v0 : (__expf(v0) - 1.f);
                v1 = v1 > 0.f ? v1 : (__expf(v1) - 1.f);
                *(float2*)(outF + base + (size_t)rr * OUTc + col) = make_float2(v0, v1);
            }
        }
    }
}

extern "C" void kernel_launch(void* const* d_in, const int* in_sizes, int n_in,
                              void* d_out, int out_size) {
    const float* x    = (const float*)d_in[0];
    const float* ax   = (const float*)d_in[1];
    const int*   adj  = (const int*)d_in[2];
    const float* WQ_w = (const float*)d_in[3];
    const float* WQ_b = (const float*)d_in[4];
    const float* a    = (const float*)d_in[5];
    const float* fc_w = (const float*)d_in[6];
    const float* fc_b = (const float*)d_in[7];
    float* out = (float*)d_out;

    prep_M<<<256, 256>>>(fc_w, WQ_w);
    prep_small<<<1, 256>>>(WQ_w, WQ_b, a, fc_w);
    conv_w<<<(OUTc * Dd) / 256, 256>>>(fc_w);

    dim3 cxg(Dd / 32, Nn / 32, Bb);
    conv_x<<<cxg, 256>>>(x, ax);

    dim3 fg(Nn / 32, Bb), fb(32, 8);
    f_kernel<<<fg, fb>>>(x, ax, a);

    // fused: z GEMM tiles (blocks 0..127) + softmax rows (blocks 128..8319)
    attz_mma<<<128 + Bb * Nn, 256>>>(adj);

    out_mma<<<dim3(OUTc / 128, Nn / 128, Bb), 256>>>(fc_b, out);
}

// round 12
// speedup vs baseline: 1.2135x; 1.2135x over previous
#include <cuda_runtime.h>
#include <cuda_bf16.h>
#include <stdint.h>
#include <math.h>

#define Bb   8
#define Nn   1024
#define INc  256
#define AXc  512
#define Dd   768
#define OUTc 256
#define ALPHA 0.2f
#define NEGV  -9.0e15f

typedef __nv_bfloat16 bf16;

// ---------------- scratch (static device globals; no allocation) ----------------
__device__ float g_M[OUTc * INc];
__device__ float g_v1[INc], g_v2[INc];
__device__ float g_zb[OUTc];
__device__ float g_c[2];
__device__ __align__(16) float g_f1[Bb * Nn];
__device__ __align__(16) float g_f2[Bb * Nn];

__device__ __align__(16) bf16 g_att_h[(size_t)Bb * Nn * Nn];
__device__ __align__(16) bf16 g_att_l[(size_t)Bb * Nn * Nn];
__device__ __align__(16) bf16 g_X_h[(size_t)Bb * Nn * Dd];
__device__ __align__(16) bf16 g_X_l[(size_t)Bb * Nn * Dd];
__device__ __align__(16) bf16 g_W_h[OUTc * Dd];
__device__ __align__(16) bf16 g_W_l[OUTc * Dd];
__device__ __align__(16) bf16 g_z_h[(size_t)Bb * OUTc * Nn];
__device__ __align__(16) bf16 g_z_l[(size_t)Bb * OUTc * Nn];

__device__ __forceinline__ void split_bf16(float v, bf16& h, bf16& l) {
    h = __float2bfloat16(v);
    l = __float2bfloat16(v - __bfloat162float(h));
}

__device__ __forceinline__ uint32_t pack2(bf16 a, bf16 b) {
    return (uint32_t)__bfloat16_as_ushort(a) | ((uint32_t)__bfloat16_as_ushort(b) << 16);
}

__device__ __forceinline__ void ldsm4(uint32_t& r0, uint32_t& r1, uint32_t& r2,
                                      uint32_t& r3, uint32_t addr) {
    asm volatile(
        "ldmatrix.sync.aligned.m8n8.x4.shared.b16 {%0,%1,%2,%3}, [%4];"
        : "=r"(r0), "=r"(r1), "=r"(r2), "=r"(r3) : "r"(addr));
}

__device__ __forceinline__ void mma16816(float& c0, float& c1, float& c2, float& c3,
                                         uint32_t a0, uint32_t a1, uint32_t a2, uint32_t a3,
                                         uint32_t b0, uint32_t b1) {
    asm volatile(
        "mma.sync.aligned.m16n8k16.row.col.f32.bf16.bf16.f32 "
        "{%0,%1,%2,%3},{%4,%5,%6,%7},{%8,%9},{%0,%1,%2,%3};"
        : "+f"(c0), "+f"(c1), "+f"(c2), "+f"(c3)
        : "r"(a0), "r"(a1), "r"(a2), "r"(a3), "r"(b0), "r"(b1));
}

// ---------------- prep ----------------
__global__ void prep_M(const float* __restrict__ fc_w, const float* __restrict__ WQ) {
    int o = blockIdx.x, k = threadIdx.x;
    const float* fr = fc_w + o * Dd;
    float s = 0.f;
    for (int t = 0; t < INc; ++t) s += fr[t] * WQ[t * INc + k];
    g_M[o * INc + k] = s;
}

__global__ void prep_small(const float* __restrict__ WQ, const float* __restrict__ WQb,
                           const float* __restrict__ a, const float* __restrict__ fc_w) {
    int t = threadIdx.x;
    float s1 = 0.f, s2 = 0.f;
    for (int r = 0; r < INc; ++r) {
        float w = WQ[r * INc + t];
        s1 += w * a[r];
        s2 += w * a[Dd + r];
    }
    g_v1[t] = s1; g_v2[t] = s2;
    const float* fr = fc_w + t * Dd;
    float z = 0.f;
    for (int r = 0; r < INc; ++r) z += WQb[r] * fr[r];
    g_zb[t] = z;
    __shared__ float r1[256], r2[256];
    r1[t] = WQb[t] * a[t];
    r2[t] = WQb[t] * a[Dd + t];
    __syncthreads();
    for (int st = 128; st > 0; st >>= 1) {
        if (t < st) { r1[t] += r1[t + st]; r2[t] += r2[t + st]; }
        __syncthreads();
    }
    if (t == 0) { g_c[0] = r1[0]; g_c[1] = r2[0]; }
}

__global__ void conv_w(const float* __restrict__ fc_w) {
    int idx = blockIdx.x * 256 + threadIdx.x;
    int o = idx / Dd, k = idx - o * Dd;
    float v = (k < INc) ? g_M[o * INc + k] : fc_w[o * Dd + k];
    bf16 h, l; split_bf16(v, h, l);
    g_W_h[idx] = h; g_W_l[idx] = l;
}

__global__ __launch_bounds__(256) void conv_x(const float* __restrict__ x,
                                              const float* __restrict__ ax) {
    __shared__ float tile[32][33];
    int b = blockIdx.z;
    int k0 = blockIdx.x * 32, n0 = blockIdx.y * 32;
    int t = threadIdx.x;
    int tn = t & 31, tk = t >> 5;
    #pragma unroll
    for (int u = 0; u < 4; ++u) {
        int kk = k0 + tk + 8 * u;
        float vv = (kk < INc) ? x[((size_t)b * INc + kk) * Nn + n0 + tn]
                              : ax[((size_t)b * AXc + (kk - INc)) * Nn + n0 + tn];
        tile[tk + 8 * u][tn] = vv;
    }
    __syncthreads();
    int wn = t >> 3, wk = (t & 7) * 4;
    bf16 h[4], l[4];
    #pragma unroll
    for (int u = 0; u < 4; ++u) split_bf16(tile[wk + u][wn], h[u], l[u]);
    size_t idx = ((size_t)b * Nn + n0 + wn) * Dd + k0 + wk;
    *(uint2*)(g_X_h + idx) = make_uint2(pack2(h[0], h[1]), pack2(h[2], h[3]));
    *(uint2*)(g_X_l + idx) = make_uint2(pack2(l[0], l[1]), pack2(l[2], l[3]));
}

// ---------------- f1/f2 ----------------
__global__ void f_kernel(const float* __restrict__ x, const float* __restrict__ ax,
                         const float* __restrict__ a) {
    int b  = blockIdx.y;
    int n  = blockIdx.x * 32 + threadIdx.x;
    int ty = threadIdx.y;
    const float* xb  = x  + (size_t)b * INc * Nn;
    const float* axb = ax + (size_t)b * AXc * Nn;
    float s1 = 0.f, s2 = 0.f;
    for (int k = ty; k < INc; k += 8) {
        float v = xb[k * Nn + n];
        s1 += v * g_v1[k];
        s2 += v * g_v2[k];
    }
    for (int c = ty; c < AXc; c += 8) {
        float v = axb[c * Nn + n];
        s1 += v * a[INc + c];
        s2 += v * a[Dd + INc + c];
    }
    __shared__ float r1[8][32], r2[8][32];
    r1[ty][threadIdx.x] = s1;
    r2[ty][threadIdx.x] = s2;
    __syncthreads();
    if (ty == 0) {
        float t1 = 0.f, t2 = 0.f;
        #pragma unroll
        for (int u = 0; u < 8; ++u) { t1 += r1[u][threadIdx.x]; t2 += r2[u][threadIdx.x]; }
        g_f1[b * Nn + n] = t1 + g_c[0];
        g_f2[b * Nn + n] = t2 + g_c[1];
    }
}

// ---------------- masked softmax rows -> bf16 hi/lo ----------------
__global__ __launch_bounds__(256) void att_kernel(const int* __restrict__ adj) {
    int b = blockIdx.y, i = blockIdx.x;
    int t = threadIdx.x;
    int lane = t & 31, warp = t >> 5;
    float f1v = g_f1[b * Nn + i];
    const int4*   arow = (const int4*)(adj + ((size_t)b * Nn + i) * Nn);
    const float4* f2r  = (const float4*)(g_f2 + b * Nn);
    float4 f2 = f2r[t];
    int4   ad = arow[t];
    float v[4];
    v[0] = f1v + f2.x; v[1] = f1v + f2.y; v[2] = f1v + f2.z; v[3] = f1v + f2.w;
    #pragma unroll
    for (int q = 0; q < 4; ++q) v[q] = v[q] > 0.f ? v[q] : ALPHA * v[q];
    v[0] = (ad.x > 0) ? v[0] : NEGV;
    v[1] = (ad.y > 0) ? v[1] : NEGV;
    v[2] = (ad.z > 0) ? v[2] : NEGV;
    v[3] = (ad.w > 0) ? v[3] : NEGV;

    float m = fmaxf(fmaxf(v[0], v[1]), fmaxf(v[2], v[3]));
    #pragma unroll
    for (int o = 16; o > 0; o >>= 1) m = fmaxf(m, __shfl_xor_sync(0xffffffffu, m, o));
    __shared__ float redm[8], reds[8];
    if (lane == 0) redm[warp] = m;
    __syncthreads();
    m = redm[0];
    #pragma unroll
    for (int u = 1; u < 8; ++u) m = fmaxf(m, redm[u]);

    float p[4], s = 0.f;
    #pragma unroll
    for (int q = 0; q < 4; ++q) { p[q] = __expf(v[q] - m); s += p[q]; }
    #pragma unroll
    for (int o = 16; o > 0; o >>= 1) s += __shfl_xor_sync(0xffffffffu, s, o);
    if (lane == 0) reds[warp] = s;
    __syncthreads();
    s = reds[0];
    #pragma unroll
    for (int u = 1; u < 8; ++u) s += reds[u];
    float inv = 1.f / s;

    bf16 h[4], l[4];
    #pragma unroll
    for (int q = 0; q < 4; ++q) split_bf16(p[q] * inv, h[q], l[q]);
    size_t base = ((size_t)b * Nn + i) * Nn + t * 4;
    *(uint2*)(g_att_h + base) = make_uint2(pack2(h[0], h[1]), pack2(h[2], h[3]));
    *(uint2*)(g_att_l + base) = make_uint2(pack2(l[0], l[1]), pack2(l[2], l[3]));
}

// ---------------- tensor-core GEMMs, double-buffered ----------------
#define SROW 24
#define BUFB (128 * SROW * 2)
#define BUFU (128 * 3)

// z^T[o][n] = Wcat @ Xcat^T : M=256(o), N=1024(n), K=768
__global__ __launch_bounds__(256) void z_mma() {
    const int K = Dd;
    int b  = blockIdx.z;
    int m0 = blockIdx.y * 128;
    int n0 = blockIdx.x * 128;
    const bf16* Ah = g_W_h;
    const bf16* Al = g_W_l;
    const bf16* Bh = g_X_h + (size_t)b * Nn * Dd;
    const bf16* Bl = g_X_l + (size_t)b * Nn * Dd;

    __shared__ __align__(16) bf16 sAh[2 * 128 * SROW], sAl[2 * 128 * SROW];
    __shared__ __align__(16) bf16 sBh[2 * 128 * SROW], sBl[2 * 128 * SROW];

    int t = threadIdx.x;
    int lrow = t >> 1, lhalf = t & 1;
    const bf16* pAh = Ah + (size_t)(m0 + lrow) * K + lhalf * 8;
    const bf16* pAl = Al + (size_t)(m0 + lrow) * K + lhalf * 8;
    const bf16* pBh = Bh + (size_t)(n0 + lrow) * K + lhalf * 8;
    const bf16* pBl = Bl + (size_t)(n0 + lrow) * K + lhalf * 8;
    int sidx = lrow * 3 + lhalf;

    int wid = t >> 5, lane = t & 31;
    int wm0 = (wid >> 2) * 64;
    int wn0 = (wid & 3) * 32;
    int lr = lane & 15, lc = (lane >> 4) * 8;

    uint32_t saAh = (uint32_t)__cvta_generic_to_shared(sAh);
    uint32_t saAl = (uint32_t)__cvta_generic_to_shared(sAl);
    uint32_t saBh = (uint32_t)__cvta_generic_to_shared(sBh);
    uint32_t saBl = (uint32_t)__cvta_generic_to_shared(sBl);
    uint32_t aAddrH[4], aAddrL[4], bAddrH[2], bAddrL[2];
    #pragma unroll
    for (int mb = 0; mb < 4; ++mb) {
        uint32_t off = (uint32_t)((wm0 + mb * 16 + lr) * SROW + lc) * 2;
        aAddrH[mb] = saAh + off;
        aAddrL[mb] = saAl + off;
    }
    #pragma unroll
    for (int g = 0; g < 2; ++g) {
        uint32_t off = (uint32_t)((wn0 + g * 16 + lr) * SROW + lc) * 2;
        bAddrH[g] = saBh + off;
        bAddrL[g] = saBl + off;
    }

    float acc[4][4][4];
    #pragma unroll
    for (int i = 0; i < 4; ++i)
        #pragma unroll
        for (int j = 0; j < 4; ++j)
            #pragma unroll
            for (int q = 0; q < 4; ++q) acc[i][j][q] = 0.f;

    uint4 fa  = *(const uint4*)pAh;
    uint4 fb  = *(const uint4*)pAl;
    uint4 fc4 = *(const uint4*)pBh;
    uint4 fd  = *(const uint4*)pBl;
    ((uint4*)sAh)[sidx] = fa;
    ((uint4*)sAl)[sidx] = fb;
    ((uint4*)sBh)[sidx] = fc4;
    ((uint4*)sBl)[sidx] = fd;
    __syncthreads();

    uint32_t Afh[4][4], Afl[4][4], Bfh[2][4], Bfl[2][4];
    int cur = 0;

    for (int k0 = 0; k0 < K; k0 += 16) {
        bool has_next = (k0 + 16 < K);
        if (has_next) {
            fa  = *(const uint4*)(pAh + k0 + 16);
            fb  = *(const uint4*)(pAl + k0 + 16);
            fc4 = *(const uint4*)(pBh + k0 + 16);
            fd  = *(const uint4*)(pBl + k0 + 16);
        }
        uint32_t co = (uint32_t)cur * BUFB;
        #pragma unroll
        for (int mb = 0; mb < 4; ++mb) {
            ldsm4(Afh[mb][0], Afh[mb][1], Afh[mb][2], Afh[mb][3], aAddrH[mb] + co);
            ldsm4(Afl[mb][0], Afl[mb][1], Afl[mb][2], Afl[mb][3], aAddrL[mb] + co);
        }
        #pragma unroll
        for (int g = 0; g < 2; ++g) {
            ldsm4(Bfh[g][0], Bfh[g][1], Bfh[g][2], Bfh[g][3], bAddrH[g] + co);
            ldsm4(Bfl[g][0], Bfl[g][1], Bfl[g][2], Bfl[g][3], bAddrL[g] + co);
        }
        #pragma unroll
        for (int mb = 0; mb < 4; ++mb) {
            #pragma unroll
            for (int j = 0; j < 4; ++j) {
                int g = j >> 1, p = j & 1;
                float* C = acc[mb][j];
                mma16816(C[0], C[1], C[2], C[3],
                         Afh[mb][0], Afh[mb][1], Afh[mb][2], Afh[mb][3],
                         Bfh[g][p], Bfh[g][p + 2]);
                mma16816(C[0], C[1], C[2], C[3],
                         Afh[mb][0], Afh[mb][1], Afh[mb][2], Afh[mb][3],
                         Bfl[g][p], Bfl[g][p + 2]);
                mma16816(C[0], C[1], C[2], C[3],
                         Afl[mb][0], Afl[mb][1], Afl[mb][2], Afl[mb][3],
                         Bfh[g][p], Bfh[g][p + 2]);
            }
        }
        if (has_next) {
            int nidx = (cur ^ 1) * BUFU + sidx;
            ((uint4*)sAh)[nidx] = fa;
            ((uint4*)sAl)[nidx] = fb;
            ((uint4*)sBh)[nidx] = fc4;
            ((uint4*)sBl)[nidx] = fd;
        }
        __syncthreads();
        cur ^= 1;
    }

    int r_lo = lane >> 2, c_off = (lane & 3) * 2;
    size_t base = (size_t)b * OUTc * Nn;
    #pragma unroll
    for (int mb = 0; mb < 4; ++mb) {
        #pragma unroll
        for (int j = 0; j < 4; ++j) {
            int row = m0 + wm0 + mb * 16 + r_lo;
            int col = n0 + wn0 + j * 8 + c_off;
            float* C = acc[mb][j];
            #pragma unroll
            for (int h = 0; h < 2; ++h) {
                int rr = row + h * 8;
                float bz = g_zb[rr];
                float v0 = C[h * 2 + 0] + bz;
                float v1 = C[h * 2 + 1] + bz;
                bf16 h0, l0, h1, l1;
                split_bf16(v0, h0, l0);
                split_bf16(v1, h1, l1);
                size_t idx = base + (size_t)rr * Nn + col;
                *(uint32_t*)(g_z_h + idx) = pack2(h0, h1);
                *(uint32_t*)(g_z_l + idx) = pack2(l0, l1);
            }
        }
    }
}

// out[i][o] = elu(att @ z^T + fc_b) : M=1024(i), N=256(o), K=1024
__global__ __launch_bounds__(256) void out_mma(const float* __restrict__ bias,
                                               float* __restrict__ outF) {
    const int K = Nn;
    int b  = blockIdx.z;
    int m0 = blockIdx.y * 128;
    int n0 = blockIdx.x * 128;
    const bf16* Ah = g_att_h + (size_t)b * Nn * Nn;
    const bf16* Al = g_att_l + (size_t)b * Nn * Nn;
    const bf16* Bh = g_z_h + (size_t)b * OUTc * Nn;
    const bf16* Bl = g_z_l + (size_t)b * OUTc * Nn;

    __shared__ __align__(16) bf16 sAh[2 * 128 * SROW], sAl[2 * 128 * SROW];
    __shared__ __align__(16) bf16 sBh[2 * 128 * SROW], sBl[2 * 128 * SROW];

    int t = threadIdx.x;
    int lrow = t >> 1, lhalf = t & 1;
    const bf16* pAh = Ah + (size_t)(m0 + lrow) * K + lhalf * 8;
    const bf16* pAl = Al + (size_t)(m0 + lrow) * K + lhalf * 8;
    const bf16* pBh = Bh + (size_t)(n0 + lrow) * K + lhalf * 8;
    const bf16* pBl = Bl + (size_t)(n0 + lrow) * K + lhalf * 8;
    int sidx = lrow * 3 + lhalf;

    int wid = t >> 5, lane = t & 31;
    int wm0 = (wid >> 2) * 64;
    int wn0 = (wid & 3) * 32;
    int lr = lane & 15, lc = (lane >> 4) * 8;

    uint32_t saAh = (uint32_t)__cvta_generic_to_shared(sAh);
    uint32_t saAl = (uint32_t)__cvta_generic_to_shared(sAl);
    uint32_t saBh = (uint32_t)__cvta_generic_to_shared(sBh);
    uint32_t saBl = (uint32_t)__cvta_generic_to_shared(sBl);
    uint32_t aAddrH[4], aAddrL[4], bAddrH[2], bAddrL[2];
    #pragma unroll
    for (int mb = 0; mb < 4; ++mb) {
        uint32_t off = (uint32_t)((wm0 + mb * 16 + lr) * SROW + lc) * 2;
        aAddrH[mb] = saAh + off;
        aAddrL[mb] = saAl + off;
    }
    #pragma unroll
    for (int g = 0; g < 2; ++g) {
        uint32_t off = (uint32_t)((wn0 + g * 16 + lr) * SROW + lc) * 2;
        bAddrH[g] = saBh + off;
        bAddrL[g] = saBl + off;
    }

    float acc[4][4][4];
    #pragma unroll
    for (int i = 0; i < 4; ++i)
        #pragma unroll
        for (int j = 0; j < 4; ++j)
            #pragma unroll
            for (int q = 0; q < 4; ++q) acc[i][j][q] = 0.f;

    uint4 fa  = *(const uint4*)pAh;
    uint4 fb  = *(const uint4*)pAl;
    uint4 fc4 = *(const uint4*)pBh;
    uint4 fd  = *(const uint4*)pBl;
    ((uint4*)sAh)[sidx] = fa;
    ((uint4*)sAl)[sidx] = fb;
    ((uint4*)sBh)[sidx] = fc4;
    ((uint4*)sBl)[sidx] = fd;
    __syncthreads();

    uint32_t Afh[4][4], Afl[4][4], Bfh[2][4], Bfl[2][4];
    int cur = 0;

    for (int k0 = 0; k0 < K; k0 += 16) {
        bool has_next = (k0 + 16 < K);
        if (has_next) {
            fa  = *(const uint4*)(pAh + k0 + 16);
            fb  = *(const uint4*)(pAl + k0 + 16);
            fc4 = *(const uint4*)(pBh + k0 + 16);
            fd  = *(const uint4*)(pBl + k0 + 16);
        }
        uint32_t co = (uint32_t)cur * BUFB;
        #pragma unroll
        for (int mb = 0; mb < 4; ++mb) {
            ldsm4(Afh[mb][0], Afh[mb][1], Afh[mb][2], Afh[mb][3], aAddrH[mb] + co);
            ldsm4(Afl[mb][0], Afl[mb][1], Afl[mb][2], Afl[mb][3], aAddrL[mb] + co);
        }
        #pragma unroll
        for (int g = 0; g < 2; ++g) {
            ldsm4(Bfh[g][0], Bfh[g][1], Bfh[g][2], Bfh[g][3], bAddrH[g] + co);
            ldsm4(Bfl[g][0], Bfl[g][1], Bfl[g][2], Bfl[g][3], bAddrL[g] + co);
        }
        #pragma unroll
        for (int mb = 0; mb < 4; ++mb) {
            #pragma unroll
            for (int j = 0; j < 4; ++j) {
                int g = j >> 1, p = j & 1;
                float* C = acc[mb][j];
                mma16816(C[0], C[1], C[2], C[3],
                         Afh[mb][0], Afh[mb][1], Afh[mb][2], Afh[mb][3],
                         Bfh[g][p], Bfh[g][p + 2]);
                mma16816(C[0], C[1], C[2], C[3],
                         Afh[mb][0], Afh[mb][1], Afh[mb][2], Afh[mb][3],
                         Bfl[g][p], Bfl[g][p + 2]);
                mma16816(C[0], C[1], C[2], C[3],
                         Afl[mb][0], Afl[mb][1], Afl[mb][2], Afl[mb][3],
                         Bfh[g][p], Bfh[g][p + 2]);
            }
        }
        if (has_next) {
            int nidx = (cur ^ 1) * BUFU + sidx;
            ((uint4*)sAh)[nidx] = fa;
            ((uint4*)sAl)[nidx] = fb;
            ((uint4*)sBh)[nidx] = fc4;
            ((uint4*)sBl)[nidx] = fd;
        }
        __syncthreads();
        cur ^= 1;
    }

    int r_lo = lane >> 2, c_off = (lane & 3) * 2;
    size_t base = (size_t)b * Nn * OUTc;
    #pragma unroll
    for (int mb = 0; mb < 4; ++mb) {
        #pragma unroll
        for (int j = 0; j < 4; ++j) {
            int row = m0 + wm0 + mb * 16 + r_lo;
            int col = n0 + wn0 + j * 8 + c_off;
            float* C = acc[mb][j];
            #pragma unroll
            for (int h = 0; h < 2; ++h) {
                int rr = row + h * 8;
                float v0 = C[h * 2 + 0] + bias[col + 0];
                float v1 = C[h * 2 + 1] + bias[col + 1];
                v0 = v0 > 0.f ? v0 : (__expf(v0) - 1.f);
                v1 = v1 > 0.f ? v1 : (__expf(v1) - 1.f);
                *(float2*)(outF + base + (size_t)rr * OUTc + col) = make_float2(v0, v1);
            }
        }
    }
}

extern "C" void kernel_launch(void* const* d_in, const int* in_sizes, int n_in,
                              void* d_out, int out_size) {
    const float* x    = (const float*)d_in[0];
    const float* ax   = (const float*)d_in[1];
    const int*   adj  = (const int*)d_in[2];
    const float* WQ_w = (const float*)d_in[3];
    const float* WQ_b = (const float*)d_in[4];
    const float* a    = (const float*)d_in[5];
    const float* fc_w = (const float*)d_in[6];
    const float* fc_b = (const float*)d_in[7];
    float* out = (float*)d_out;

    // Fork a second stream so the z-branch (conv_w, conv_x, z_mma) runs in
    // parallel with the attention branch (f_kernel, att_kernel) in the captured
    // graph. Streams/events are created per call and intentionally NOT
    // destroyed: kernel_launch runs only twice (correctness + capture), graph
    // replays execute no host code, and destroying a forked stream mid-capture
    // would invalidate the capture. No device memory is allocated.
    cudaStream_t s1;
    cudaEvent_t eFork, eJoin;
    cudaStreamCreateWithFlags(&s1, cudaStreamNonBlocking);
    cudaEventCreateWithFlags(&eFork, cudaEventDisableTiming);
    cudaEventCreateWithFlags(&eJoin, cudaEventDisableTiming);

    // shared prep on the main (capture-origin) stream
    prep_M<<<256, 256>>>(fc_w, WQ_w);
    prep_small<<<1, 256>>>(WQ_w, WQ_b, a, fc_w);

    // fork: s1 inherits the prep dependencies
    cudaEventRecord(eFork, 0);
    cudaStreamWaitEvent(s1, eFork, 0);

    // branch B (s1): z path
    conv_w<<<(OUTc * Dd) / 256, 256, 0, s1>>>(fc_w);
    dim3 cxg(Dd / 32, Nn / 32, Bb);
    conv_x<<<cxg, 256, 0, s1>>>(x, ax);
    z_mma<<<dim3(Nn / 128, OUTc / 128, Bb), 256, 0, s1>>>();

    // branch A (main stream): attention path
    dim3 fg(Nn / 32, Bb), fb(32, 8);
    f_kernel<<<fg, fb>>>(x, ax, a);
    dim3 ag(Nn, Bb);
    att_kernel<<<ag, 256>>>(adj);

    // join: out_mma needs both att (main) and z (s1)
    cudaEventRecord(eJoin, s1);
    cudaStreamWaitEvent(0, eJoin, 0);

    out_mma<<<dim3(OUTc / 128, Nn / 128, Bb), 256>>>(fc_b, out);
}

// round 14
// speedup vs baseline: 1.4004x; 1.1540x over previous
#include <cuda_runtime.h>
#include <cuda_fp16.h>
#include <stdint.h>
#include <math.h>

#define Bb   8
#define Nn   1024
#define INc  256
#define AXc  512
#define Dd   768
#define OUTc 256
#define ALPHA 0.2f
#define NEGV  -9.0e15f

typedef __half f16;

// ---------------- scratch (static device globals; no allocation) ----------------
__device__ float g_M[OUTc * INc];
__device__ float g_v1[INc], g_v2[INc];
__device__ float g_zb[OUTc];
__device__ float g_c[2];
__device__ __align__(16) float g_f1[Bb * Nn];
__device__ __align__(16) float g_f2[Bb * Nn];

__device__ __align__(16) f16 g_att_h[(size_t)Bb * Nn * Nn];  // att hi/lo fp16
__device__ __align__(16) f16 g_att_l[(size_t)Bb * Nn * Nn];
__device__ __align__(16) f16 g_X[(size_t)Bb * Nn * Dd];      // Xcat^T single fp16
__device__ __align__(16) f16 g_W_h[OUTc * Dd];               // Wcat hi/lo fp16
__device__ __align__(16) f16 g_W_l[OUTc * Dd];
__device__ __align__(16) f16 g_z[(size_t)Bb * OUTc * Nn];    // z^T single fp16

__device__ __forceinline__ void split_f16(float v, f16& h, f16& l) {
    h = __float2half_rn(v);
    l = __float2half_rn(v - __half2float(h));
}

__device__ __forceinline__ uint32_t pack2h(f16 a, f16 b) {
    return (uint32_t)__half_as_ushort(a) | ((uint32_t)__half_as_ushort(b) << 16);
}

__device__ __forceinline__ void ldsm4(uint32_t& r0, uint32_t& r1, uint32_t& r2,
                                      uint32_t& r3, uint32_t addr) {
    asm volatile(
        "ldmatrix.sync.aligned.m8n8.x4.shared.b16 {%0,%1,%2,%3}, [%4];"
        : "=r"(r0), "=r"(r1), "=r"(r2), "=r"(r3) : "r"(addr));
}

__device__ __forceinline__ void mma16816(float& c0, float& c1, float& c2, float& c3,
                                         uint32_t a0, uint32_t a1, uint32_t a2, uint32_t a3,
                                         uint32_t b0, uint32_t b1) {
    asm volatile(
        "mma.sync.aligned.m16n8k16.row.col.f32.f16.f16.f32 "
        "{%0,%1,%2,%3},{%4,%5,%6,%7},{%8,%9},{%0,%1,%2,%3};"
        : "+f"(c0), "+f"(c1), "+f"(c2), "+f"(c3)
        : "r"(a0), "r"(a1), "r"(a2), "r"(a3), "r"(b0), "r"(b1));
}

// ---------------- prep ----------------
__global__ void prep_M(const float* __restrict__ fc_w, const float* __restrict__ WQ) {
    int o = blockIdx.x, k = threadIdx.x;
    const float* fr = fc_w + o * Dd;
    float s = 0.f;
    for (int t = 0; t < INc; ++t) s += fr[t] * WQ[t * INc + k];
    g_M[o * INc + k] = s;
}

__global__ void prep_small(const float* __restrict__ WQ, const float* __restrict__ WQb,
                           const float* __restrict__ a, const float* __restrict__ fc_w) {
    int t = threadIdx.x;
    float s1 = 0.f, s2 = 0.f;
    for (int r = 0; r < INc; ++r) {
        float w = WQ[r * INc + t];
        s1 += w * a[r];
        s2 += w * a[Dd + r];
    }
    g_v1[t] = s1; g_v2[t] = s2;
    const float* fr = fc_w + t * Dd;
    float z = 0.f;
    for (int r = 0; r < INc; ++r) z += WQb[r] * fr[r];
    g_zb[t] = z;
    __shared__ float r1[256], r2[256];
    r1[t] = WQb[t] * a[t];
    r2[t] = WQb[t] * a[Dd + t];
    __syncthreads();
    for (int st = 128; st > 0; st >>= 1) {
        if (t < st) { r1[t] += r1[t + st]; r2[t] += r2[t + st]; }
        __syncthreads();
    }
    if (t == 0) { g_c[0] = r1[0]; g_c[1] = r2[0]; }
}

__global__ void conv_w(const float* __restrict__ fc_w) {
    int idx = blockIdx.x * 256 + threadIdx.x;
    int o = idx / Dd, k = idx - o * Dd;
    float v = (k < INc) ? g_M[o * INc + k] : fc_w[o * Dd + k];
    f16 h, l; split_f16(v, h, l);
    g_W_h[idx] = h; g_W_l[idx] = l;
}

// Xcat^T: [b][n][k] single fp16, tiled transpose
__global__ __launch_bounds__(256) void conv_x(const float* __restrict__ x,
                                              const float* __restrict__ ax) {
    __shared__ float tile[32][33];
    int b = blockIdx.z;
    int k0 = blockIdx.x * 32, n0 = blockIdx.y * 32;
    int t = threadIdx.x;
    int tn = t & 31, tk = t >> 5;
    #pragma unroll
    for (int u = 0; u < 4; ++u) {
        int kk = k0 + tk + 8 * u;
        float vv = (kk < INc) ? x[((size_t)b * INc + kk) * Nn + n0 + tn]
                              : ax[((size_t)b * AXc + (kk - INc)) * Nn + n0 + tn];
        tile[tk + 8 * u][tn] = vv;
    }
    __syncthreads();
    int wn = t >> 3, wk = (t & 7) * 4;
    f16 h[4];
    #pragma unroll
    for (int u = 0; u < 4; ++u) h[u] = __float2half_rn(tile[wk + u][wn]);
    size_t idx = ((size_t)b * Nn + n0 + wn) * Dd + k0 + wk;
    *(uint2*)(g_X + idx) = make_uint2(pack2h(h[0], h[1]), pack2h(h[2], h[3]));
}

// ---------------- f1/f2 ----------------
__global__ void f_kernel(const float* __restrict__ x, const float* __restrict__ ax,
                         const float* __restrict__ a) {
    int b  = blockIdx.y;
    int n  = blockIdx.x * 32 + threadIdx.x;
    int ty = threadIdx.y;
    const float* xb  = x  + (size_t)b * INc * Nn;
    const float* axb = ax + (size_t)b * AXc * Nn;
    float s1 = 0.f, s2 = 0.f;
    for (int k = ty; k < INc; k += 8) {
        float v = xb[k * Nn + n];
        s1 += v * g_v1[k];
        s2 += v * g_v2[k];
    }
    for (int c = ty; c < AXc; c += 8) {
        float v = axb[c * Nn + n];
        s1 += v * a[INc + c];
        s2 += v * a[Dd + INc + c];
    }
    __shared__ float r1[8][32], r2[8][32];
    r1[ty][threadIdx.x] = s1;
    r2[ty][threadIdx.x] = s2;
    __syncthreads();
    if (ty == 0) {
        float t1 = 0.f, t2 = 0.f;
        #pragma unroll
        for (int u = 0; u < 8; ++u) { t1 += r1[u][threadIdx.x]; t2 += r2[u][threadIdx.x]; }
        g_f1[b * Nn + n] = t1 + g_c[0];
        g_f2[b * Nn + n] = t2 + g_c[1];
    }
}

// ---------------- masked softmax rows -> fp16 hi/lo ----------------
__global__ __launch_bounds__(256) void att_kernel(const int* __restrict__ adj) {
    int b = blockIdx.y, i = blockIdx.x;
    int t = threadIdx.x;
    int lane = t & 31, warp = t >> 5;
    float f1v = g_f1[b * Nn + i];
    const int4*   arow = (const int4*)(adj + ((size_t)b * Nn + i) * Nn);
    const float4* f2r  = (const float4*)(g_f2 + b * Nn);
    float4 f2 = f2r[t];
    int4   ad = arow[t];
    float v[4];
    v[0] = f1v + f2.x; v[1] = f1v + f2.y; v[2] = f1v + f2.z; v[3] = f1v + f2.w;
    #pragma unroll
    for (int q = 0; q < 4; ++q) v[q] = v[q] > 0.f ? v[q] : ALPHA * v[q];
    v[0] = (ad.x > 0) ? v[0] : NEGV;
    v[1] = (ad.y > 0) ? v[1] : NEGV;
    v[2] = (ad.z > 0) ? v[2] : NEGV;
    v[3] = (ad.w > 0) ? v[3] : NEGV;

    float m = fmaxf(fmaxf(v[0], v[1]), fmaxf(v[2], v[3]));
    #pragma unroll
    for (int o = 16; o > 0; o >>= 1) m = fmaxf(m, __shfl_xor_sync(0xffffffffu, m, o));
    __shared__ float redm[8], reds[8];
    if (lane == 0) redm[warp] = m;
    __syncthreads();
    m = redm[0];
    #pragma unroll
    for (int u = 1; u < 8; ++u) m = fmaxf(m, redm[u]);

    float p[4], s = 0.f;
    #pragma unroll
    for (int q = 0; q < 4; ++q) { p[q] = __expf(v[q] - m); s += p[q]; }
    #pragma unroll
    for (int o = 16; o > 0; o >>= 1) s += __shfl_xor_sync(0xffffffffu, s, o);
    if (lane == 0) reds[warp] = s;
    __syncthreads();
    s = reds[0];
    #pragma unroll
    for (int u = 1; u < 8; ++u) s += reds[u];
    float inv = 1.f / s;

    f16 h[4], l[4];
    #pragma unroll
    for (int q = 0; q < 4; ++q) split_f16(p[q] * inv, h[q], l[q]);
    size_t base = ((size_t)b * Nn + i) * Nn + t * 4;
    *(uint2*)(g_att_h + base) = make_uint2(pack2h(h[0], h[1]), pack2h(h[2], h[3]));
    *(uint2*)(g_att_l + base) = make_uint2(pack2h(l[0], l[1]), pack2h(l[2], l[3]));
}

// ---------------- tensor-core GEMMs, double-buffered, A split / B single ----------------
#define SROW 24
#define BUFB (128 * SROW * 2)
#define BUFU (128 * 3)

// z^T[o][n] = Wcat @ Xcat^T : M=256(o), N=1024(n), K=768
__global__ __launch_bounds__(256) void z_mma() {
    const int K = Dd;
    int b  = blockIdx.z;
    int m0 = blockIdx.y * 128;
    int n0 = blockIdx.x * 128;
    const f16* Ah = g_W_h;
    const f16* Al = g_W_l;
    const f16* Bs = g_X + (size_t)b * Nn * Dd;

    __shared__ __align__(16) f16 sAh[2 * 128 * SROW], sAl[2 * 128 * SROW];
    __shared__ __align__(16) f16 sB[2 * 128 * SROW];

    int t = threadIdx.x;
    int lrow = t >> 1, lhalf = t & 1;
    const f16* pAh = Ah + (size_t)(m0 + lrow) * K + lhalf * 8;
    const f16* pAl = Al + (size_t)(m0 + lrow) * K + lhalf * 8;
    const f16* pB  = Bs + (size_t)(n0 + lrow) * K + lhalf * 8;
    int sidx = lrow * 3 + lhalf;

    int wid = t >> 5, lane = t & 31;
    int wm0 = (wid >> 2) * 64;
    int wn0 = (wid & 3) * 32;
    int lr = lane & 15, lc = (lane >> 4) * 8;

    uint32_t saAh = (uint32_t)__cvta_generic_to_shared(sAh);
    uint32_t saAl = (uint32_t)__cvta_generic_to_shared(sAl);
    uint32_t saB  = (uint32_t)__cvta_generic_to_shared(sB);
    uint32_t aAddrH[4], aAddrL[4], bAddr[2];
    #pragma unroll
    for (int mb = 0; mb < 4; ++mb) {
        uint32_t off = (uint32_t)((wm0 + mb * 16 + lr) * SROW + lc) * 2;
        aAddrH[mb] = saAh + off;
        aAddrL[mb] = saAl + off;
    }
    #pragma unroll
    for (int g = 0; g < 2; ++g) {
        uint32_t off = (uint32_t)((wn0 + g * 16 + lr) * SROW + lc) * 2;
        bAddr[g] = saB + off;
    }

    float acc[4][4][4];
    #pragma unroll
    for (int i = 0; i < 4; ++i)
        #pragma unroll
        for (int j = 0; j < 4; ++j)
            #pragma unroll
            for (int q = 0; q < 4; ++q) acc[i][j][q] = 0.f;

    uint4 fa  = *(const uint4*)pAh;
    uint4 fb  = *(const uint4*)pAl;
    uint4 fc4 = *(const uint4*)pB;
    ((uint4*)sAh)[sidx] = fa;
    ((uint4*)sAl)[sidx] = fb;
    ((uint4*)sB)[sidx]  = fc4;
    __syncthreads();

    uint32_t Afh[4][4], Afl[4][4], Bf[2][4];
    int cur = 0;

    for (int k0 = 0; k0 < K; k0 += 16) {
        bool has_next = (k0 + 16 < K);
        if (has_next) {
            fa  = *(const uint4*)(pAh + k0 + 16);
            fb  = *(const uint4*)(pAl + k0 + 16);
            fc4 = *(const uint4*)(pB + k0 + 16);
        }
        uint32_t co = (uint32_t)cur * BUFB;
        #pragma unroll
        for (int mb = 0; mb < 4; ++mb) {
            ldsm4(Afh[mb][0], Afh[mb][1], Afh[mb][2], Afh[mb][3], aAddrH[mb] + co);
            ldsm4(Afl[mb][0], Afl[mb][1], Afl[mb][2], Afl[mb][3], aAddrL[mb] + co);
        }
        #pragma unroll
        for (int g = 0; g < 2; ++g) {
            ldsm4(Bf[g][0], Bf[g][1], Bf[g][2], Bf[g][3], bAddr[g] + co);
        }
        #pragma unroll
        for (int mb = 0; mb < 4; ++mb) {
            #pragma unroll
            for (int j = 0; j < 4; ++j) {
                int g = j >> 1, p = j & 1;
                float* C = acc[mb][j];
                mma16816(C[0], C[1], C[2], C[3],
                         Afh[mb][0], Afh[mb][1], Afh[mb][2], Afh[mb][3],
                         Bf[g][p], Bf[g][p + 2]);
                mma16816(C[0], C[1], C[2], C[3],
                         Afl[mb][0], Afl[mb][1], Afl[mb][2], Afl[mb][3],
                         Bf[g][p], Bf[g][p + 2]);
            }
        }
        if (has_next) {
            int nidx = (cur ^ 1) * BUFU + sidx;
            ((uint4*)sAh)[nidx] = fa;
            ((uint4*)sAl)[nidx] = fb;
            ((uint4*)sB)[nidx]  = fc4;
        }
        __syncthreads();
        cur ^= 1;
    }

    int r_lo = lane >> 2, c_off = (lane & 3) * 2;
    size_t base = (size_t)b * OUTc * Nn;
    #pragma unroll
    for (int mb = 0; mb < 4; ++mb) {
        #pragma unroll
        for (int j = 0; j < 4; ++j) {
            int row = m0 + wm0 + mb * 16 + r_lo;
            int col = n0 + wn0 + j * 8 + c_off;
            float* C = acc[mb][j];
            #pragma unroll
            for (int h = 0; h < 2; ++h) {
                int rr = row + h * 8;
                float bz = g_zb[rr];
                f16 h0 = __float2half_rn(C[h * 2 + 0] + bz);
                f16 h1 = __float2half_rn(C[h * 2 + 1] + bz);
                size_t idx = base + (size_t)rr * Nn + col;
                *(uint32_t*)(g_z + idx) = pack2h(h0, h1);
            }
        }
    }
}

// out[i][o] = elu(att @ z^T + fc_b) : M=1024(i), N=256(o), K=1024
__global__ __launch_bounds__(256) void out_mma(const float* __restrict__ bias,
                                               float* __restrict__ outF) {
    const int K = Nn;
    int b  = blockIdx.z;
    int m0 = blockIdx.y * 128;
    int n0 = blockIdx.x * 128;
    const f16* Ah = g_att_h + (size_t)b * Nn * Nn;
    const f16* Al = g_att_l + (size_t)b * Nn * Nn;
    const f16* Bs = g_z + (size_t)b * OUTc * Nn;

    __shared__ __align__(16) f16 sAh[2 * 128 * SROW], sAl[2 * 128 * SROW];
    __shared__ __align__(16) f16 sB[2 * 128 * SROW];

    int t = threadIdx.x;
    int lrow = t >> 1, lhalf = t & 1;
    const f16* pAh = Ah + (size_t)(m0 + lrow) * K + lhalf * 8;
    const f16* pAl = Al + (size_t)(m0 + lrow) * K + lhalf * 8;
    const f16* pB  = Bs + (size_t)(n0 + lrow) * K + lhalf * 8;
    int sidx = lrow * 3 + lhalf;

    int wid = t >> 5, lane = t & 31;
    int wm0 = (wid >> 2) * 64;
    int wn0 = (wid & 3) * 32;
    int lr = lane & 15, lc = (lane >> 4) * 8;

    uint32_t saAh = (uint32_t)__cvta_generic_to_shared(sAh);
    uint32_t saAl = (uint32_t)__cvta_generic_to_shared(sAl);
    uint32_t saB  = (uint32_t)__cvta_generic_to_shared(sB);
    uint32_t aAddrH[4], aAddrL[4], bAddr[2];
    #pragma unroll
    for (int mb = 0; mb < 4; ++mb) {
        uint32_t off = (uint32_t)((wm0 + mb * 16 + lr) * SROW + lc) * 2;
        aAddrH[mb] = saAh + off;
        aAddrL[mb] = saAl + off;
    }
    #pragma unroll
    for (int g = 0; g < 2; ++g) {
        uint32_t off = (uint32_t)((wn0 + g * 16 + lr) * SROW + lc) * 2;
        bAddr[g] = saB + off;
    }

    float acc[4][4][4];
    #pragma unroll
    for (int i = 0; i < 4; ++i)
        #pragma unroll
        for (int j = 0; j < 4; ++j)
            #pragma unroll
            for (int q = 0; q < 4; ++q) acc[i][j][q] = 0.f;

    uint4 fa  = *(const uint4*)pAh;
    uint4 fb  = *(const uint4*)pAl;
    uint4 fc4 = *(const uint4*)pB;
    ((uint4*)sAh)[sidx] = fa;
    ((uint4*)sAl)[sidx] = fb;
    ((uint4*)sB)[sidx]  = fc4;
    __syncthreads();

    uint32_t Afh[4][4], Afl[4][4], Bf[2][4];
    int cur = 0;

    for (int k0 = 0; k0 < K; k0 += 16) {
        bool has_next = (k0 + 16 < K);
        if (has_next) {
            fa  = *(const uint4*)(pAh + k0 + 16);
            fb  = *(const uint4*)(pAl + k0 + 16);
            fc4 = *(const uint4*)(pB + k0 + 16);
        }
        uint32_t co = (uint32_t)cur * BUFB;
        #pragma unroll
        for (int mb = 0; mb < 4; ++mb) {
            ldsm4(Afh[mb][0], Afh[mb][1], Afh[mb][2], Afh[mb][3], aAddrH[mb] + co);
            ldsm4(Afl[mb][0], Afl[mb][1], Afl[mb][2], Afl[mb][3], aAddrL[mb] + co);
        }
        #pragma unroll
        for (int g = 0; g < 2; ++g) {
            ldsm4(Bf[g][0], Bf[g][1], Bf[g][2], Bf[g][3], bAddr[g] + co);
        }
        #pragma unroll
        for (int mb = 0; mb < 4; ++mb) {
            #pragma unroll
            for (int j = 0; j < 4; ++j) {
                int g = j >> 1, p = j & 1;
                float* C = acc[mb][j];
                mma16816(C[0], C[1], C[2], C[3],
                         Afh[mb][0], Afh[mb][1], Afh[mb][2], Afh[mb][3],
                         Bf[g][p], Bf[g][p + 2]);
                mma16816(C[0], C[1], C[2], C[3],
                         Afl[mb][0], Afl[mb][1], Afl[mb][2], Afl[mb][3],
                         Bf[g][p], Bf[g][p + 2]);
            }
        }
        if (has_next) {
            int nidx = (cur ^ 1) * BUFU + sidx;
            ((uint4*)sAh)[nidx] = fa;
            ((uint4*)sAl)[nidx] = fb;
            ((uint4*)sB)[nidx]  = fc4;
        }
        __syncthreads();
        cur ^= 1;
    }

    int r_lo = lane >> 2, c_off = (lane & 3) * 2;
    size_t base = (size_t)b * Nn * OUTc;
    #pragma unroll
    for (int mb = 0; mb < 4; ++mb) {
        #pragma unroll
        for (int j = 0; j < 4; ++j) {
            int row = m0 + wm0 + mb * 16 + r_lo;
            int col = n0 + wn0 + j * 8 + c_off;
            float* C = acc[mb][j];
            #pragma unroll
            for (int h = 0; h < 2; ++h) {
                int rr = row + h * 8;
                float v0 = C[h * 2 + 0] + bias[col + 0];
                float v1 = C[h * 2 + 1] + bias[col + 1];
                v0 = v0 > 0.f ? v0 : (__expf(v0) - 1.f);
                v1 = v1 > 0.f ? v1 : (__expf(v1) - 1.f);
                *(float2*)(outF + base + (size_t)rr * OUTc + col) = make_float2(v0, v1);
            }
        }
    }
}

extern "C" void kernel_launch(void* const* d_in, const int* in_sizes, int n_in,
                              void* d_out, int out_size) {
    const float* x    = (const float*)d_in[0];
    const float* ax   = (const float*)d_in[1];
    const int*   adj  = (const int*)d_in[2];
    const float* WQ_w = (const float*)d_in[3];
    const float* WQ_b = (const float*)d_in[4];
    const float* a    = (const float*)d_in[5];
    const float* fc_w = (const float*)d_in[6];
    const float* fc_b = (const float*)d_in[7];
    float* out = (float*)d_out;

    prep_M<<<256, 256>>>(fc_w, WQ_w);
    prep_small<<<1, 256>>>(WQ_w, WQ_b, a, fc_w);
    conv_w<<<(OUTc * Dd) / 256, 256>>>(fc_w);

    dim3 cxg(Dd / 32, Nn / 32, Bb);
    conv_x<<<cxg, 256>>>(x, ax);

    dim3 fg(Nn / 32, Bb), fb(32, 8);
    f_kernel<<<fg, fb>>>(x, ax, a);

    dim3 ag(Nn, Bb);
    att_kernel<<<ag, 256>>>(adj);

    z_mma<<<dim3(Nn / 128, OUTc / 128, Bb), 256>>>();
    out_mma<<<dim3(OUTc / 128, Nn / 128, Bb), 256>>>(fc_b, out);
}

// round 16
// speedup vs baseline: 1.5608x; 1.1146x over previous
#include <cuda_runtime.h>
#include <cuda_fp16.h>
#include <stdint.h>
#include <math.h>

#define Bb   8
#define Nn   1024
#define INc  256
#define AXc  512
#define Dd   768
#define OUTc 256
#define ALPHA 0.2f
#define NEGV  -9.0e15f

typedef __half f16;

// ---------------- scratch (static device globals; no allocation) ----------------
__device__ float g_M[OUTc * INc];
__device__ float g_v1[INc], g_v2[INc];
__device__ float g_zb[OUTc];
__device__ float g_c[2];
__device__ __align__(16) float g_f1[Bb * Nn];
__device__ __align__(16) float g_f2[Bb * Nn];

__device__ __align__(16) f16 g_att[(size_t)Bb * Nn * Nn];  // att single fp16
__device__ __align__(16) f16 g_X[(size_t)Bb * Nn * Dd];    // Xcat^T single fp16
__device__ __align__(16) f16 g_W[OUTc * Dd];               // Wcat single fp16
__device__ __align__(16) f16 g_z[(size_t)Bb * OUTc * Nn];  // z^T single fp16

__device__ __forceinline__ uint32_t pack2h(f16 a, f16 b) {
    return (uint32_t)__half_as_ushort(a) | ((uint32_t)__half_as_ushort(b) << 16);
}

__device__ __forceinline__ void ldsm4(uint32_t& r0, uint32_t& r1, uint32_t& r2,
                                      uint32_t& r3, uint32_t addr) {
    asm volatile(
        "ldmatrix.sync.aligned.m8n8.x4.shared.b16 {%0,%1,%2,%3}, [%4];"
        : "=r"(r0), "=r"(r1), "=r"(r2), "=r"(r3) : "r"(addr));
}

__device__ __forceinline__ void mma16816(float& c0, float& c1, float& c2, float& c3,
                                         uint32_t a0, uint32_t a1, uint32_t a2, uint32_t a3,
                                         uint32_t b0, uint32_t b1) {
    asm volatile(
        "mma.sync.aligned.m16n8k16.row.col.f32.f16.f16.f32 "
        "{%0,%1,%2,%3},{%4,%5,%6,%7},{%8,%9},{%0,%1,%2,%3};"
        : "+f"(c0), "+f"(c1), "+f"(c2), "+f"(c3)
        : "r"(a0), "r"(a1), "r"(a2), "r"(a3), "r"(b0), "r"(b1));
}

// ---------------- prep ----------------
__global__ void prep_M(const float* __restrict__ fc_w, const float* __restrict__ WQ) {
    int o = blockIdx.x, k = threadIdx.x;
    const float* fr = fc_w + o * Dd;
    float s = 0.f;
    for (int t = 0; t < INc; ++t) s += fr[t] * WQ[t * INc + k];
    g_M[o * INc + k] = s;
}

__global__ void prep_small(const float* __restrict__ WQ, const float* __restrict__ WQb,
                           const float* __restrict__ a, const float* __restrict__ fc_w) {
    int t = threadIdx.x;
    float s1 = 0.f, s2 = 0.f;
    for (int r = 0; r < INc; ++r) {
        float w = WQ[r * INc + t];
        s1 += w * a[r];
        s2 += w * a[Dd + r];
    }
    g_v1[t] = s1; g_v2[t] = s2;
    const float* fr = fc_w + t * Dd;
    float z = 0.f;
    for (int r = 0; r < INc; ++r) z += WQb[r] * fr[r];
    g_zb[t] = z;
    __shared__ float r1[256], r2[256];
    r1[t] = WQb[t] * a[t];
    r2[t] = WQb[t] * a[Dd + t];
    __syncthreads();
    for (int st = 128; st > 0; st >>= 1) {
        if (t < st) { r1[t] += r1[t + st]; r2[t] += r2[t + st]; }
        __syncthreads();
    }
    if (t == 0) { g_c[0] = r1[0]; g_c[1] = r2[0]; }
}

__global__ void conv_w(const float* __restrict__ fc_w) {
    int idx = blockIdx.x * 256 + threadIdx.x;
    int o = idx / Dd, k = idx - o * Dd;
    float v = (k < INc) ? g_M[o * INc + k] : fc_w[o * Dd + k];
    g_W[idx] = __float2half_rn(v);
}

// Xcat^T: [b][n][k] single fp16, tiled transpose
__global__ __launch_bounds__(256) void conv_x(const float* __restrict__ x,
                                              const float* __restrict__ ax) {
    __shared__ float tile[32][33];
    int b = blockIdx.z;
    int k0 = blockIdx.x * 32, n0 = blockIdx.y * 32;
    int t = threadIdx.x;
    int tn = t & 31, tk = t >> 5;
    #pragma unroll
    for (int u = 0; u < 4; ++u) {
        int kk = k0 + tk + 8 * u;
        float vv = (kk < INc) ? x[((size_t)b * INc + kk) * Nn + n0 + tn]
                              : ax[((size_t)b * AXc + (kk - INc)) * Nn + n0 + tn];
        tile[tk + 8 * u][tn] = vv;
    }
    __syncthreads();
    int wn = t >> 3, wk = (t & 7) * 4;
    f16 h[4];
    #pragma unroll
    for (int u = 0; u < 4; ++u) h[u] = __float2half_rn(tile[wk + u][wn]);
    size_t idx = ((size_t)b * Nn + n0 + wn) * Dd + k0 + wk;
    *(uint2*)(g_X + idx) = make_uint2(pack2h(h[0], h[1]), pack2h(h[2], h[3]));
}

// ---------------- f1/f2 ----------------
__global__ void f_kernel(const float* __restrict__ x, const float* __restrict__ ax,
                         const float* __restrict__ a) {
    int b  = blockIdx.y;
    int n  = blockIdx.x * 32 + threadIdx.x;
    int ty = threadIdx.y;
    const float* xb  = x  + (size_t)b * INc * Nn;
    const float* axb = ax + (size_t)b * AXc * Nn;
    float s1 = 0.f, s2 = 0.f;
    for (int k = ty; k < INc; k += 8) {
        float v = xb[k * Nn + n];
        s1 += v * g_v1[k];
        s2 += v * g_v2[k];
    }
    for (int c = ty; c < AXc; c += 8) {
        float v = axb[c * Nn + n];
        s1 += v * a[INc + c];
        s2 += v * a[Dd + INc + c];
    }
    __shared__ float r1[8][32], r2[8][32];
    r1[ty][threadIdx.x] = s1;
    r2[ty][threadIdx.x] = s2;
    __syncthreads();
    if (ty == 0) {
        float t1 = 0.f, t2 = 0.f;
        #pragma unroll
        for (int u = 0; u < 8; ++u) { t1 += r1[u][threadIdx.x]; t2 += r2[u][threadIdx.x]; }
        g_f1[b * Nn + n] = t1 + g_c[0];
        g_f2[b * Nn + n] = t2 + g_c[1];
    }
}

// ---------------- masked softmax rows -> single fp16 ----------------
__global__ __launch_bounds__(256) void att_kernel(const int* __restrict__ adj) {
    int b = blockIdx.y, i = blockIdx.x;
    int t = threadIdx.x;
    int lane = t & 31, warp = t >> 5;
    float f1v = g_f1[b * Nn + i];
    const int4*   arow = (const int4*)(adj + ((size_t)b * Nn + i) * Nn);
    const float4* f2r  = (const float4*)(g_f2 + b * Nn);
    float4 f2 = f2r[t];
    int4   ad = arow[t];
    float v[4];
    v[0] = f1v + f2.x; v[1] = f1v + f2.y; v[2] = f1v + f2.z; v[3] = f1v + f2.w;
    #pragma unroll
    for (int q = 0; q < 4; ++q) v[q] = v[q] > 0.f ? v[q] : ALPHA * v[q];
    v[0] = (ad.x > 0) ? v[0] : NEGV;
    v[1] = (ad.y > 0) ? v[1] : NEGV;
    v[2] = (ad.z > 0) ? v[2] : NEGV;
    v[3] = (ad.w > 0) ? v[3] : NEGV;

    float m = fmaxf(fmaxf(v[0], v[1]), fmaxf(v[2], v[3]));
    #pragma unroll
    for (int o = 16; o > 0; o >>= 1) m = fmaxf(m, __shfl_xor_sync(0xffffffffu, m, o));
    __shared__ float redm[8], reds[8];
    if (lane == 0) redm[warp] = m;
    __syncthreads();
    m = redm[0];
    #pragma unroll
    for (int u = 1; u < 8; ++u) m = fmaxf(m, redm[u]);

    float p[4], s = 0.f;
    #pragma unroll
    for (int q = 0; q < 4; ++q) { p[q] = __expf(v[q] - m); s += p[q]; }
    #pragma unroll
    for (int o = 16; o > 0; o >>= 1) s += __shfl_xor_sync(0xffffffffu, s, o);
    if (lane == 0) reds[warp] = s;
    __syncthreads();
    s = reds[0];
    #pragma unroll
    for (int u = 1; u < 8; ++u) s += reds[u];
    float inv = 1.f / s;

    f16 h[4];
    #pragma unroll
    for (int q = 0; q < 4; ++q) h[q] = __float2half_rn(p[q] * inv);
    size_t base = ((size_t)b * Nn + i) * Nn + t * 4;
    *(uint2*)(g_att + base) = make_uint2(pack2h(h[0], h[1]), pack2h(h[2], h[3]));
}

// ---------------- tensor-core GEMMs, double-buffered, pure single fp16 ----------------
#define SROW 24
#define BUFB (128 * SROW * 2)
#define BUFU (128 * 3)

// z^T[o][n] = Wcat @ Xcat^T : M=256(o), N=1024(n), K=768
__global__ __launch_bounds__(256) void z_mma() {
    const int K = Dd;
    int b  = blockIdx.z;
    int m0 = blockIdx.y * 128;
    int n0 = blockIdx.x * 128;
    const f16* As = g_W;
    const f16* Bs = g_X + (size_t)b * Nn * Dd;

    __shared__ __align__(16) f16 sA[2 * 128 * SROW];
    __shared__ __align__(16) f16 sB[2 * 128 * SROW];

    int t = threadIdx.x;
    int lrow = t >> 1, lhalf = t & 1;
    const f16* pA = As + (size_t)(m0 + lrow) * K + lhalf * 8;
    const f16* pB = Bs + (size_t)(n0 + lrow) * K + lhalf * 8;
    int sidx = lrow * 3 + lhalf;

    int wid = t >> 5, lane = t & 31;
    int wm0 = (wid >> 2) * 64;
    int wn0 = (wid & 3) * 32;
    int lr = lane & 15, lc = (lane >> 4) * 8;

    uint32_t saA = (uint32_t)__cvta_generic_to_shared(sA);
    uint32_t saB = (uint32_t)__cvta_generic_to_shared(sB);
    uint32_t aAddr[4], bAddr[2];
    #pragma unroll
    for (int mb = 0; mb < 4; ++mb)
        aAddr[mb] = saA + (uint32_t)((wm0 + mb * 16 + lr) * SROW + lc) * 2;
    #pragma unroll
    for (int g = 0; g < 2; ++g)
        bAddr[g] = saB + (uint32_t)((wn0 + g * 16 + lr) * SROW + lc) * 2;

    float acc[4][4][4];
    #pragma unroll
    for (int i = 0; i < 4; ++i)
        #pragma unroll
        for (int j = 0; j < 4; ++j)
            #pragma unroll
            for (int q = 0; q < 4; ++q) acc[i][j][q] = 0.f;

    uint4 fa  = *(const uint4*)pA;
    uint4 fc4 = *(const uint4*)pB;
    ((uint4*)sA)[sidx] = fa;
    ((uint4*)sB)[sidx] = fc4;
    __syncthreads();

    uint32_t Af[4][4], Bf[2][4];
    int cur = 0;

    for (int k0 = 0; k0 < K; k0 += 16) {
        bool has_next = (k0 + 16 < K);
        if (has_next) {
            fa  = *(const uint4*)(pA + k0 + 16);
            fc4 = *(const uint4*)(pB + k0 + 16);
        }
        uint32_t co = (uint32_t)cur * BUFB;
        #pragma unroll
        for (int mb = 0; mb < 4; ++mb)
            ldsm4(Af[mb][0], Af[mb][1], Af[mb][2], Af[mb][3], aAddr[mb] + co);
        #pragma unroll
        for (int g = 0; g < 2; ++g)
            ldsm4(Bf[g][0], Bf[g][1], Bf[g][2], Bf[g][3], bAddr[g] + co);
        #pragma unroll
        for (int mb = 0; mb < 4; ++mb) {
            #pragma unroll
            for (int j = 0; j < 4; ++j) {
                int g = j >> 1, p = j & 1;
                float* C = acc[mb][j];
                mma16816(C[0], C[1], C[2], C[3],
                         Af[mb][0], Af[mb][1], Af[mb][2], Af[mb][3],
                         Bf[g][p], Bf[g][p + 2]);
            }
        }
        if (has_next) {
            int nidx = (cur ^ 1) * BUFU + sidx;
            ((uint4*)sA)[nidx] = fa;
            ((uint4*)sB)[nidx] = fc4;
        }
        __syncthreads();
        cur ^= 1;
    }

    int r_lo = lane >> 2, c_off = (lane & 3) * 2;
    size_t base = (size_t)b * OUTc * Nn;
    #pragma unroll
    for (int mb = 0; mb < 4; ++mb) {
        #pragma unroll
        for (int j = 0; j < 4; ++j) {
            int row = m0 + wm0 + mb * 16 + r_lo;
            int col = n0 + wn0 + j * 8 + c_off;
            float* C = acc[mb][j];
            #pragma unroll
            for (int h = 0; h < 2; ++h) {
                int rr = row + h * 8;
                float bz = g_zb[rr];
                f16 h0 = __float2half_rn(C[h * 2 + 0] + bz);
                f16 h1 = __float2half_rn(C[h * 2 + 1] + bz);
                size_t idx = base + (size_t)rr * Nn + col;
                *(uint32_t*)(g_z + idx) = pack2h(h0, h1);
            }
        }
    }
}

// out[i][o] = elu(att @ z^T + fc_b) : M=1024(i), N=256(o), K=1024
__global__ __launch_bounds__(256) void out_mma(const float* __restrict__ bias,
                                               float* __restrict__ outF) {
    const int K = Nn;
    int b  = blockIdx.z;
    int m0 = blockIdx.y * 128;
    int n0 = blockIdx.x * 128;
    const f16* As = g_att + (size_t)b * Nn * Nn;
    const f16* Bs = g_z + (size_t)b * OUTc * Nn;

    __shared__ __align__(16) f16 sA[2 * 128 * SROW];
    __shared__ __align__(16) f16 sB[2 * 128 * SROW];

    int t = threadIdx.x;
    int lrow = t >> 1, lhalf = t & 1;
    const f16* pA = As + (size_t)(m0 + lrow) * K + lhalf * 8;
    const f16* pB = Bs + (size_t)(n0 + lrow) * K + lhalf * 8;
    int sidx = lrow * 3 + lhalf;

    int wid = t >> 5, lane = t & 31;
    int wm0 = (wid >> 2) * 64;
    int wn0 = (wid & 3) * 32;
    int lr = lane & 15, lc = (lane >> 4) * 8;

    uint32_t saA = (uint32_t)__cvta_generic_to_shared(sA);
    uint32_t saB = (uint32_t)__cvta_generic_to_shared(sB);
    uint32_t aAddr[4], bAddr[2];
    #pragma unroll
    for (int mb = 0; mb < 4; ++mb)
        aAddr[mb] = saA + (uint32_t)((wm0 + mb * 16 + lr) * SROW + lc) * 2;
    #pragma unroll
    for (int g = 0; g < 2; ++g)
        bAddr[g] = saB + (uint32_t)((wn0 + g * 16 + lr) * SROW + lc) * 2;

    float acc[4][4][4];
    #pragma unroll
    for (int i = 0; i < 4; ++i)
        #pragma unroll
        for (int j = 0; j < 4; ++j)
            #pragma unroll
            for (int q = 0; q < 4; ++q) acc[i][j][q] = 0.f;

    uint4 fa  = *(const uint4*)pA;
    uint4 fc4 = *(const uint4*)pB;
    ((uint4*)sA)[sidx] = fa;
    ((uint4*)sB)[sidx] = fc4;
    __syncthreads();

    uint32_t Af[4][4], Bf[2][4];
    int cur = 0;

    for (int k0 = 0; k0 < K; k0 += 16) {
        bool has_next = (k0 + 16 < K);
        if (has_next) {
            fa  = *(const uint4*)(pA + k0 + 16);
            fc4 = *(const uint4*)(pB + k0 + 16);
        }
        uint32_t co = (uint32_t)cur * BUFB;
        #pragma unroll
        for (int mb = 0; mb < 4; ++mb)
            ldsm4(Af[mb][0], Af[mb][1], Af[mb][2], Af[mb][3], aAddr[mb] + co);
        #pragma unroll
        for (int g = 0; g < 2; ++g)
            ldsm4(Bf[g][0], Bf[g][1], Bf[g][2], Bf[g][3], bAddr[g] + co);
        #pragma unroll
        for (int mb = 0; mb < 4; ++mb) {
            #pragma unroll
            for (int j = 0; j < 4; ++j) {
                int g = j >> 1, p = j & 1;
                float* C = acc[mb][j];
                mma16816(C[0], C[1], C[2], C[3],
                         Af[mb][0], Af[mb][1], Af[mb][2], Af[mb][3],
                         Bf[g][p], Bf[g][p + 2]);
            }
        }
        if (has_next) {
            int nidx = (cur ^ 1) * BUFU + sidx;
            ((uint4*)sA)[nidx] = fa;
            ((uint4*)sB)[nidx] = fc4;
        }
        __syncthreads();
        cur ^= 1;
    }

    int r_lo = lane >> 2, c_off = (lane & 3) * 2;
    size_t base = (size_t)b * Nn * OUTc;
    #pragma unroll
    for (int mb = 0; mb < 4; ++mb) {
        #pragma unroll
        for (int j = 0; j < 4; ++j) {
            int row = m0 + wm0 + mb * 16 + r_lo;
            int col = n0 + wn0 + j * 8 + c_off;
            float* C = acc[mb][j];
            #pragma unroll
            for (int h = 0; h < 2; ++h) {
                int rr = row + h * 8;
                float v0 = C[h * 2 + 0] + bias[col + 0];
                float v1 = C[h * 2 + 1] + bias[col + 1];
                v0 = v0 > 0.f ? v0 : (__expf(v0) - 1.f);
                v1 = v1 > 0.f ? v1 : (__expf(v1) - 1.f);
                *(float2*)(outF + base + (size_t)rr * OUTc + col) = make_float2(v0, v1);
            }
        }
    }
}

extern "C" void kernel_launch(void* const* d_in, const int* in_sizes, int n_in,
                              void* d_out, int out_size) {
    const float* x    = (const float*)d_in[0];
    const float* ax   = (const float*)d_in[1];
    const int*   adj  = (const int*)d_in[2];
    const float* WQ_w = (const float*)d_in[3];
    const float* WQ_b = (const float*)d_in[4];
    const float* a    = (const float*)d_in[5];
    const float* fc_w = (const float*)d_in[6];
    const float* fc_b = (const float*)d_in[7];
    float* out = (float*)d_out;

    prep_M<<<256, 256>>>(fc_w, WQ_w);
    prep_small<<<1, 256>>>(WQ_w, WQ_b, a, fc_w);
    conv_w<<<(OUTc * Dd) / 256, 256>>>(fc_w);

    dim3 cxg(Dd / 32, Nn / 32, Bb);
    conv_x<<<cxg, 256>>>(x, ax);

    dim3 fg(Nn / 32, Bb), fb(32, 8);
    f_kernel<<<fg, fb>>>(x, ax, a);

    dim3 ag(Nn, Bb);
    att_kernel<<<ag, 256>>>(adj);

    z_mma<<<dim3(Nn / 128, OUTc / 128, Bb), 256>>>();
    out_mma<<<dim3(OUTc / 128, Nn / 128, Bb), 256>>>(fc_b, out);
}

// round 17
// speedup vs baseline: 1.6754x; 1.0734x over previous
#include <cuda_runtime.h>
#include <cuda_fp16.h>
#include <stdint.h>
#include <math.h>

#define Bb   8
#define Nn   1024
#define INc  256
#define AXc  512
#define Dd   768
#define OUTc 256
#define ALPHA 0.2f
#define NEGV  -9.0e15f

typedef __half f16;

// ---------------- scratch (static device globals; no allocation) ----------------
__device__ float g_M[OUTc * INc];
__device__ float g_v1[INc], g_v2[INc];
__device__ float g_zb[OUTc];
__device__ float g_c[2];
__device__ __align__(16) float g_f1[Bb * Nn];
__device__ __align__(16) float g_f2[Bb * Nn];

__device__ __align__(16) f16 g_att[(size_t)Bb * Nn * Nn];  // att single fp16
__device__ __align__(16) f16 g_X[(size_t)Bb * Nn * Dd];    // Xcat^T single fp16
__device__ __align__(16) f16 g_W[OUTc * Dd];               // Wcat single fp16
__device__ __align__(16) f16 g_z[(size_t)Bb * OUTc * Nn];  // z^T single fp16

__device__ __forceinline__ uint32_t pack2h(f16 a, f16 b) {
    return (uint32_t)__half_as_ushort(a) | ((uint32_t)__half_as_ushort(b) << 16);
}

__device__ __forceinline__ void ldsm4(uint32_t& r0, uint32_t& r1, uint32_t& r2,
                                      uint32_t& r3, uint32_t addr) {
    asm volatile(
        "ldmatrix.sync.aligned.m8n8.x4.shared.b16 {%0,%1,%2,%3}, [%4];"
        : "=r"(r0), "=r"(r1), "=r"(r2), "=r"(r3) : "r"(addr));
}

__device__ __forceinline__ void mma16816(float& c0, float& c1, float& c2, float& c3,
                                         uint32_t a0, uint32_t a1, uint32_t a2, uint32_t a3,
                                         uint32_t b0, uint32_t b1) {
    asm volatile(
        "mma.sync.aligned.m16n8k16.row.col.f32.f16.f16.f32 "
        "{%0,%1,%2,%3},{%4,%5,%6,%7},{%8,%9},{%0,%1,%2,%3};"
        : "+f"(c0), "+f"(c1), "+f"(c2), "+f"(c3)
        : "r"(a0), "r"(a1), "r"(a2), "r"(a3), "r"(b0), "r"(b1));
}

// ---------------- prep ----------------
__global__ void prep_M(const float* __restrict__ fc_w, const float* __restrict__ WQ) {
    int o = blockIdx.x, k = threadIdx.x;
    const float* fr = fc_w + o * Dd;
    float s = 0.f;
    for (int t = 0; t < INc; ++t) s += fr[t] * WQ[t * INc + k];
    g_M[o * INc + k] = s;
}

__global__ void prep_small(const float* __restrict__ WQ, const float* __restrict__ WQb,
                           const float* __restrict__ a, const float* __restrict__ fc_w) {
    int t = threadIdx.x;
    float s1 = 0.f, s2 = 0.f;
    for (int r = 0; r < INc; ++r) {
        float w = WQ[r * INc + t];
        s1 += w * a[r];
        s2 += w * a[Dd + r];
    }
    g_v1[t] = s1; g_v2[t] = s2;
    const float* fr = fc_w + t * Dd;
    float z = 0.f;
    for (int r = 0; r < INc; ++r) z += WQb[r] * fr[r];
    g_zb[t] = z;
    __shared__ float r1[256], r2[256];
    r1[t] = WQb[t] * a[t];
    r2[t] = WQb[t] * a[Dd + t];
    __syncthreads();
    for (int st = 128; st > 0; st >>= 1) {
        if (t < st) { r1[t] += r1[t + st]; r2[t] += r2[t + st]; }
        __syncthreads();
    }
    if (t == 0) { g_c[0] = r1[0]; g_c[1] = r2[0]; }
}

__global__ void zero_f() {
    int i = blockIdx.x * 256 + threadIdx.x;
    g_f1[i] = 0.f;
    g_f2[i] = 0.f;
}

__global__ void conv_w(const float* __restrict__ fc_w) {
    int idx = blockIdx.x * 256 + threadIdx.x;
    int o = idx / Dd, k = idx - o * Dd;
    float v = (k < INc) ? g_M[o * INc + k] : fc_w[o * Dd + k];
    g_W[idx] = __float2half_rn(v);
}

// Xcat^T transpose->fp16, FUSED with f1/f2 partial reduction (atomicAdd)
__global__ __launch_bounds__(256) void conv_x(const float* __restrict__ x,
                                              const float* __restrict__ ax,
                                              const float* __restrict__ a) {
    __shared__ float tile[32][33];
    __shared__ float r1[8][32], r2[8][32];
    int b = blockIdx.z;
    int k0 = blockIdx.x * 32, n0 = blockIdx.y * 32;
    int t = threadIdx.x;
    int tn = t & 31, tk = t >> 5;
    #pragma unroll
    for (int u = 0; u < 4; ++u) {
        int kk = k0 + tk + 8 * u;
        float vv = (kk < INc) ? x[((size_t)b * INc + kk) * Nn + n0 + tn]
                              : ax[((size_t)b * AXc + (kk - INc)) * Nn + n0 + tn];
        tile[tk + 8 * u][tn] = vv;
    }
    __syncthreads();
    // phase 2: transposed fp16 store
    int wn = t >> 3, wk = (t & 7) * 4;
    f16 h[4];
    #pragma unroll
    for (int u = 0; u < 4; ++u) h[u] = __float2half_rn(tile[wk + u][wn]);
    size_t idx = ((size_t)b * Nn + n0 + wn) * Dd + k0 + wk;
    *(uint2*)(g_X + idx) = make_uint2(pack2h(h[0], h[1]), pack2h(h[2], h[3]));
    // phase 3: f1/f2 partials over this k-slab
    float s1 = 0.f, s2 = 0.f;
    #pragma unroll
    for (int u = 0; u < 4; ++u) {
        int kl = tk * 4 + u;
        int kg = k0 + kl;
        float v = tile[kl][tn];
        float w1 = (kg < INc) ? g_v1[kg] : a[kg];
        float w2 = (kg < INc) ? g_v2[kg] : a[Dd + kg];
        s1 += v * w1;
        s2 += v * w2;
    }
    r1[tk][tn] = s1;
    r2[tk][tn] = s2;
    __syncthreads();
    if (t < 32) {
        float t1 = 0.f, t2 = 0.f;
        #pragma unroll
        for (int u = 0; u < 8; ++u) { t1 += r1[u][t]; t2 += r2[u][t]; }
        atomicAdd(&g_f1[b * Nn + n0 + t], t1);
        atomicAdd(&g_f2[b * Nn + n0 + t], t2);
    }
}

// ---------------- masked softmax rows -> single fp16 ----------------
__global__ __launch_bounds__(256) void att_kernel(const int* __restrict__ adj) {
    int b = blockIdx.y, i = blockIdx.x;
    int t = threadIdx.x;
    int lane = t & 31, warp = t >> 5;
    float cc = g_c[0] + g_c[1];
    float f1v = g_f1[b * Nn + i] + cc;
    const int4*   arow = (const int4*)(adj + ((size_t)b * Nn + i) * Nn);
    const float4* f2r  = (const float4*)(g_f2 + b * Nn);
    float4 f2 = f2r[t];
    int4   ad = arow[t];
    float v[4];
    v[0] = f1v + f2.x; v[1] = f1v + f2.y; v[2] = f1v + f2.z; v[3] = f1v + f2.w;
    #pragma unroll
    for (int q = 0; q < 4; ++q) v[q] = v[q] > 0.f ? v[q] : ALPHA * v[q];
    v[0] = (ad.x > 0) ? v[0] : NEGV;
    v[1] = (ad.y > 0) ? v[1] : NEGV;
    v[2] = (ad.z > 0) ? v[2] : NEGV;
    v[3] = (ad.w > 0) ? v[3] : NEGV;

    float m = fmaxf(fmaxf(v[0], v[1]), fmaxf(v[2], v[3]));
    #pragma unroll
    for (int o = 16; o > 0; o >>= 1) m = fmaxf(m, __shfl_xor_sync(0xffffffffu, m, o));
    __shared__ float redm[8], reds[8];
    if (lane == 0) redm[warp] = m;
    __syncthreads();
    m = redm[0];
    #pragma unroll
    for (int u = 1; u < 8; ++u) m = fmaxf(m, redm[u]);

    float p[4], s = 0.f;
    #pragma unroll
    for (int q = 0; q < 4; ++q) { p[q] = __expf(v[q] - m); s += p[q]; }
    #pragma unroll
    for (int o = 16; o > 0; o >>= 1) s += __shfl_xor_sync(0xffffffffu, s, o);
    if (lane == 0) reds[warp] = s;
    __syncthreads();
    s = reds[0];
    #pragma unroll
    for (int u = 1; u < 8; ++u) s += reds[u];
    float inv = 1.f / s;

    f16 h[4];
    #pragma unroll
    for (int q = 0; q < 4; ++q) h[q] = __float2half_rn(p[q] * inv);
    size_t base = ((size_t)b * Nn + i) * Nn + t * 4;
    *(uint2*)(g_att + base) = make_uint2(pack2h(h[0], h[1]), pack2h(h[2], h[3]));
}

// ---------------- tensor-core GEMMs: 128x64 tiles, double-buffered fp16 ----------------
#define SROW 24
#define ABUFB (128 * SROW * 2)
#define BBUFB (64 * SROW * 2)
#define ABUFU (128 * 3)
#define BBUFU (64 * 3)

// z^T[o][n] = Wcat @ Xcat^T : M=256(o)->2, N=1024(n)->16 tiles, K=768
__global__ __launch_bounds__(256) void z_mma() {
    const int K = Dd;
    int b  = blockIdx.z;
    int m0 = blockIdx.y * 128;
    int n0 = blockIdx.x * 64;
    const f16* As = g_W;
    const f16* Bs = g_X + (size_t)b * Nn * Dd;

    __shared__ __align__(16) f16 sA[2 * 128 * SROW];
    __shared__ __align__(16) f16 sB[2 * 64 * SROW];

    int t = threadIdx.x;
    int lrow = t >> 1, lhalf = t & 1;
    const f16* pA = As + (size_t)(m0 + lrow) * K + lhalf * 8;
    bool bload = (t < 128);
    const f16* pB = Bs + (size_t)(n0 + (lrow & 63)) * K + lhalf * 8;
    int sidx = lrow * 3 + lhalf;

    int wid = t >> 5, lane = t & 31;
    int wm0 = (wid >> 1) * 32;
    int wn0 = (wid & 1) * 32;
    int lr = lane & 15, lc = (lane >> 4) * 8;

    uint32_t saA = (uint32_t)__cvta_generic_to_shared(sA);
    uint32_t saB = (uint32_t)__cvta_generic_to_shared(sB);
    uint32_t aAddr[2], bAddr[2];
    #pragma unroll
    for (int mb = 0; mb < 2; ++mb)
        aAddr[mb] = saA + (uint32_t)((wm0 + mb * 16 + lr) * SROW + lc) * 2;
    #pragma unroll
    for (int g = 0; g < 2; ++g)
        bAddr[g] = saB + (uint32_t)((wn0 + g * 16 + lr) * SROW + lc) * 2;

    float acc[2][4][4];
    #pragma unroll
    for (int i = 0; i < 2; ++i)
        #pragma unroll
        for (int j = 0; j < 4; ++j)
            #pragma unroll
            for (int q = 0; q < 4; ++q) acc[i][j][q] = 0.f;

    uint4 fa = *(const uint4*)pA;
    uint4 fb4 = make_uint4(0, 0, 0, 0);
    if (bload) fb4 = *(const uint4*)pB;
    ((uint4*)sA)[sidx] = fa;
    if (bload) ((uint4*)sB)[sidx] = fb4;
    __syncthreads();

    uint32_t Af[2][4], Bf[2][4];
    int cur = 0;

    for (int k0 = 0; k0 < K; k0 += 16) {
        bool has_next = (k0 + 16 < K);
        if (has_next) {
            fa = *(const uint4*)(pA + k0 + 16);
            if (bload) fb4 = *(const uint4*)(pB + k0 + 16);
        }
        uint32_t coA = (uint32_t)cur * ABUFB;
        uint32_t coB = (uint32_t)cur * BBUFB;
        #pragma unroll
        for (int mb = 0; mb < 2; ++mb)
            ldsm4(Af[mb][0], Af[mb][1], Af[mb][2], Af[mb][3], aAddr[mb] + coA);
        #pragma unroll
        for (int g = 0; g < 2; ++g)
            ldsm4(Bf[g][0], Bf[g][1], Bf[g][2], Bf[g][3], bAddr[g] + coB);
        #pragma unroll
        for (int mb = 0; mb < 2; ++mb) {
            #pragma unroll
            for (int j = 0; j < 4; ++j) {
                int g = j >> 1, p = j & 1;
                float* C = acc[mb][j];
                mma16816(C[0], C[1], C[2], C[3],
                         Af[mb][0], Af[mb][1], Af[mb][2], Af[mb][3],
                         Bf[g][p], Bf[g][p + 2]);
            }
        }
        if (has_next) {
            ((uint4*)sA)[(cur ^ 1) * ABUFU + sidx] = fa;
            if (bload) ((uint4*)sB)[(cur ^ 1) * BBUFU + sidx] = fb4;
        }
        __syncthreads();
        cur ^= 1;
    }

    int r_lo = lane >> 2, c_off = (lane & 3) * 2;
    size_t base = (size_t)b * OUTc * Nn;
    #pragma unroll
    for (int mb = 0; mb < 2; ++mb) {
        #pragma unroll
        for (int j = 0; j < 4; ++j) {
            int row = m0 + wm0 + mb * 16 + r_lo;
            int col = n0 + wn0 + j * 8 + c_off;
            float* C = acc[mb][j];
            #pragma unroll
            for (int h = 0; h < 2; ++h) {
                int rr = row + h * 8;
                float bz = g_zb[rr];
                f16 h0 = __float2half_rn(C[h * 2 + 0] + bz);
                f16 h1 = __float2half_rn(C[h * 2 + 1] + bz);
                size_t idx = base + (size_t)rr * Nn + col;
                *(uint32_t*)(g_z + idx) = pack2h(h0, h1);
            }
        }
    }
}

// out[i][o] = elu(att @ z^T + fc_b) : M=1024(i)->8, N=256(o)->4 tiles, K=1024
__global__ __launch_bounds__(256) void out_mma(const float* __restrict__ bias,
                                               float* __restrict__ outF) {
    const int K = Nn;
    int b  = blockIdx.z;
    int m0 = blockIdx.y * 128;
    int n0 = blockIdx.x * 64;
    const f16* As = g_att + (size_t)b * Nn * Nn;
    const f16* Bs = g_z + (size_t)b * OUTc * Nn;

    __shared__ __align__(16) f16 sA[2 * 128 * SROW];
    __shared__ __align__(16) f16 sB[2 * 64 * SROW];

    int t = threadIdx.x;
    int lrow = t >> 1, lhalf = t & 1;
    const f16* pA = As + (size_t)(m0 + lrow) * K + lhalf * 8;
    bool bload = (t < 128);
    const f16* pB = Bs + (size_t)(n0 + (lrow & 63)) * K + lhalf * 8;
    int sidx = lrow * 3 + lhalf;

    int wid = t >> 5, lane = t & 31;
    int wm0 = (wid >> 1) * 32;
    int wn0 = (wid & 1) * 32;
    int lr = lane & 15, lc = (lane >> 4) * 8;

    uint32_t saA = (uint32_t)__cvta_generic_to_shared(sA);
    uint32_t saB = (uint32_t)__cvta_generic_to_shared(sB);
    uint32_t aAddr[2], bAddr[2];
    #pragma unroll
    for (int mb = 0; mb < 2; ++mb)
        aAddr[mb] = saA + (uint32_t)((wm0 + mb * 16 + lr) * SROW + lc) * 2;
    #pragma unroll
    for (int g = 0; g < 2; ++g)
        bAddr[g] = saB + (uint32_t)((wn0 + g * 16 + lr) * SROW + lc) * 2;

    float acc[2][4][4];
    #pragma unroll
    for (int i = 0; i < 2; ++i)
        #pragma unroll
        for (int j = 0; j < 4; ++j)
            #pragma unroll
            for (int q = 0; q < 4; ++q) acc[i][j][q] = 0.f;

    uint4 fa = *(const uint4*)pA;
    uint4 fb4 = make_uint4(0, 0, 0, 0);
    if (bload) fb4 = *(const uint4*)pB;
    ((uint4*)sA)[sidx] = fa;
    if (bload) ((uint4*)sB)[sidx] = fb4;
    __syncthreads();

    uint32_t Af[2][4], Bf[2][4];
    int cur = 0;

    for (int k0 = 0; k0 < K; k0 += 16) {
        bool has_next = (k0 + 16 < K);
        if (has_next) {
            fa = *(const uint4*)(pA + k0 + 16);
            if (bload) fb4 = *(const uint4*)(pB + k0 + 16);
        }
        uint32_t coA = (uint32_t)cur * ABUFB;
        uint32_t coB = (uint32_t)cur * BBUFB;
        #pragma unroll
        for (int mb = 0; mb < 2; ++mb)
            ldsm4(Af[mb][0], Af[mb][1], Af[mb][2], Af[mb][3], aAddr[mb] + coA);
        #pragma unroll
        for (int g = 0; g < 2; ++g)
            ldsm4(Bf[g][0], Bf[g][1], Bf[g][2], Bf[g][3], bAddr[g] + coB);
        #pragma unroll
        for (int mb = 0; mb < 2; ++mb) {
            #pragma unroll
            for (int j = 0; j < 4; ++j) {
                int g = j >> 1, p = j & 1;
                float* C = acc[mb][j];
                mma16816(C[0], C[1], C[2], C[3],
                         Af[mb][0], Af[mb][1], Af[mb][2], Af[mb][3],
                         Bf[g][p], Bf[g][p + 2]);
            }
        }
        if (has_next) {
            ((uint4*)sA)[(cur ^ 1) * ABUFU + sidx] = fa;
            if (bload) ((uint4*)sB)[(cur ^ 1) * BBUFU + sidx] = fb4;
        }
        __syncthreads();
        cur ^= 1;
    }

    int r_lo = lane >> 2, c_off = (lane & 3) * 2;
    size_t base = (size_t)b * Nn * OUTc;
    #pragma unroll
    for (int mb = 0; mb < 2; ++mb) {
        #pragma unroll
        for (int j = 0; j < 4; ++j) {
            int row = m0 + wm0 + mb * 16 + r_lo;
            int col = n0 + wn0 + j * 8 + c_off;
            float* C = acc[mb][j];
            #pragma unroll
            for (int h = 0; h < 2; ++h) {
                int rr = row + h * 8;
                float v0 = C[h * 2 + 0] + bias[col + 0];
                float v1 = C[h * 2 + 1] + bias[col + 1];
                v0 = v0 > 0.f ? v0 : (__expf(v0) - 1.f);
                v1 = v1 > 0.f ? v1 : (__expf(v1) - 1.f);
                *(float2*)(outF + base + (size_t)rr * OUTc + col) = make_float2(v0, v1);
            }
        }
    }
}

extern "C" void kernel_launch(void* const* d_in, const int* in_sizes, int n_in,
                              void* d_out, int out_size) {
    const float* x    = (const float*)d_in[0];
    const float* ax   = (const float*)d_in[1];
    const int*   adj  = (const int*)d_in[2];
    const float* WQ_w = (const float*)d_in[3];
    const float* WQ_b = (const float*)d_in[4];
    const float* a    = (const float*)d_in[5];
    const float* fc_w = (const float*)d_in[6];
    const float* fc_b = (const float*)d_in[7];
    float* out = (float*)d_out;

    prep_M<<<256, 256>>>(fc_w, WQ_w);
    prep_small<<<1, 256>>>(WQ_w, WQ_b, a, fc_w);
    zero_f<<<(Bb * Nn) / 256, 256>>>();
    conv_w<<<(OUTc * Dd) / 256, 256>>>(fc_w);

    dim3 cxg(Dd / 32, Nn / 32, Bb);
    conv_x<<<cxg, 256>>>(x, ax, a);

    dim3 ag(Nn, Bb);
    att_kernel<<<ag, 256>>>(adj);

    z_mma<<<dim3(Nn / 64, OUTc / 128, Bb), 256>>>();
    out_mma<<<dim3(OUTc / 64, Nn / 128, Bb), 256>>>(fc_b, out);
}